// round 2
// baseline (speedup 1.0000x reference)
#include <cuda_runtime.h>
#include <cuda_bf16.h>
#include <math.h>

// ---------------- problem constants ----------------
#define BB 2
#define HEADS 8
#define DH 32
#define ADIM 256
#define NKTOT 2240          // 1024 + 960 + 256
#define NQTOT 1600          // 1024 + 576
#define KPD 1024            // 8*8*16
#define VPD 2048            // 8*8*32
#define QPD 1024
#define VHD 256             // VPD / HEADS

// ---------------- scratch buffers (static device allocs) ----------------
__device__ float g_kseq[BB*NKTOT*KPD];          // 4,587,520
__device__ float g_vseq[BB*NKTOT*VPD];          // 9,175,040
__device__ float g_qseq[BB*NQTOT*QPD];          // 3,276,800
__device__ float g_khid[BB*NKTOT*ADIM];
__device__ float g_kemb[BB*NKTOT*ADIM];
__device__ float g_qhid[BB*NQTOT*ADIM];
__device__ float g_qemb[BB*NQTOT*ADIM];
__device__ float g_scores[(size_t)BB*HEADS*NQTOT*NKTOT];      // 57,344,000
__device__ float g_weighted[(size_t)BB*3*HEADS*NQTOT*VHD];    // 19,660,800
__device__ float g_x0[BB*96*256*256];           // 12,582,912
__device__ float g_x1[BB*96*192*192];           // 7,077,888
__device__ float g_hid1[(size_t)BB*384*256*256];// 50,331,648
__device__ float g_hid2[(size_t)BB*384*256*256];

__device__ __forceinline__ float gelu_f(float x){
    return 0.5f*x*(1.0f + tanhf(0.7978845608028654f*(x + 0.044715f*x*x*x)));
}

// ---------------- patchify: NCHW image -> [b, n, (ph,pw,c)] ----------------
__global__ void k_patchify(const float* __restrict__ src, float* __restrict__ dst,
                           int C, int Himg, int Wimg, int nOff, int Ntot, int featDim, int total)
{
    int idx = blockIdx.x*blockDim.x + threadIdx.x;
    if (idx >= total) return;
    int x = idx % Wimg;
    int t = idx / Wimg;
    int y = t % Himg; t /= Himg;
    int c = t % C;    int b = t / C;
    int hp = y>>3, ph = y&7, wp = x>>3, pw = x&7;
    int n = hp*(Wimg>>3) + wp;
    int f = ((ph<<3)+pw)*C + c;
    dst[(size_t)(b*Ntot + nOff + n)*featDim + f] = src[idx];
}

// ---------------- layernorm rows (in place) ----------------
__global__ void k_layernorm(float* __restrict__ v, const float* __restrict__ g,
                            const float* __restrict__ bta, int dim)
{
    float* p = v + (size_t)blockIdx.x*dim;
    __shared__ float red[256];
    int tid = threadIdx.x;
    float s=0.f, s2=0.f;
    for (int i=tid;i<dim;i+=256){ float x=p[i]; s+=x; s2+=x*x; }
    red[tid]=s; __syncthreads();
    for (int o=128;o>0;o>>=1){ if(tid<o) red[tid]+=red[tid+o]; __syncthreads(); }
    float mean = red[0]/dim; __syncthreads();
    red[tid]=s2; __syncthreads();
    for (int o=128;o>0;o>>=1){ if(tid<o) red[tid]+=red[tid+o]; __syncthreads(); }
    float var = red[0]/dim - mean*mean;
    float rstd = rsqrtf(var + 1e-5f);
    for (int i=tid;i<dim;i+=256){ float x=p[i]; p[i]=(x-mean)*rstd*g[i]+bta[i]; }
}

// ---------------- generic tiled GEMM body: C = act(A@B + bias) ----------------
// BM=BN=64, BK=16, 256 threads, 4x4 per thread. Requires M%64==0, N%64==0, K%16==0.
__device__ __forceinline__ void gemm_body(
    const float* __restrict__ A, int lda,
    const float* __restrict__ Bm, int ldb,
    const float* __restrict__ bias,
    float* __restrict__ C, int ldc,
    int K, int act, int bm, int bn)
{
    __shared__ float As[16][65];
    __shared__ float Bs[16][65];
    int tid = threadIdx.x;
    int tx = tid & 15, ty = tid >> 4;
    int ra = tid>>2, ca=(tid&3)<<2;
    int rb = tid>>4, cb=(tid&15)<<2;
    float acc[4][4];
    #pragma unroll
    for(int i=0;i<4;i++)
        #pragma unroll
        for(int j=0;j<4;j++) acc[i][j]=0.f;

    for (int k0=0;k0<K;k0+=16){
        float4 av = *(const float4*)(A + (size_t)(bm+ra)*lda + k0 + ca);
        As[ca  ][ra]=av.x; As[ca+1][ra]=av.y; As[ca+2][ra]=av.z; As[ca+3][ra]=av.w;
        float4 bv = *(const float4*)(Bm + (size_t)(k0+rb)*ldb + bn + cb);
        Bs[rb][cb  ]=bv.x; Bs[rb][cb+1]=bv.y; Bs[rb][cb+2]=bv.z; Bs[rb][cb+3]=bv.w;
        __syncthreads();
        #pragma unroll
        for(int kk=0;kk<16;kk++){
            float a[4], b[4];
            #pragma unroll
            for(int i=0;i<4;i++) a[i]=As[kk][(ty<<2)+i];
            #pragma unroll
            for(int j=0;j<4;j++) b[j]=Bs[kk][(tx<<2)+j];
            #pragma unroll
            for(int i=0;i<4;i++)
                #pragma unroll
                for(int j=0;j<4;j++) acc[i][j] += a[i]*b[j];
        }
        __syncthreads();
    }
    #pragma unroll
    for(int i=0;i<4;i++){
        #pragma unroll
        for(int j=0;j<4;j++){
            float v2 = acc[i][j];
            if (bias) v2 += bias[bn + (tx<<2) + j];
            if (act==1) v2 = gelu_f(v2);
            C[(size_t)(bm + (ty<<2) + i)*ldc + bn + (tx<<2) + j] = v2;
        }
    }
}

__global__ void k_gemm(const float* __restrict__ A, int lda,
                       const float* __restrict__ Bm, int ldb,
                       const float* __restrict__ bias,
                       float* __restrict__ C, int ldc, int K, int act)
{
    gemm_body(A, lda, Bm, ldb, bias, C, ldc, K, act, blockIdx.y<<6, blockIdx.x<<6);
}

// ---------------- A*V per (b, seg, head) ----------------
__global__ void k_av()
{
    int z = blockIdx.z;
    int h = z & 7; int t = z >> 3; int seg = t % 3; int b = t / 3;
    const int segOff[3] = {0, 1024, 1984};
    const int segN[3]   = {1024, 960, 256};
    const float* A = g_scores + (size_t)(b*HEADS + h)*NQTOT*NKTOT + segOff[seg];
    const float* Bv = g_vseq + ((size_t)b*NKTOT + segOff[seg])*VPD + h*VHD;
    float* C = g_weighted + (size_t)((b*3 + seg)*HEADS + h)*NQTOT*VHD;
    gemm_body(A, NKTOT, Bv, VPD, nullptr, C, VHD, segN[seg], 0, blockIdx.y<<6, blockIdx.x<<6);
}

// ---------------- Q @ K^T (d=32) ----------------
__global__ void k_qk()
{
    __shared__ float Qs[64][33];
    __shared__ float Ks[64][33];
    int z = blockIdx.z; int b = z>>3, h = z&7;
    const float* Qb = g_qemb + (size_t)b*NQTOT*ADIM + h*DH;
    const float* Kb = g_kemb + (size_t)b*NKTOT*ADIM + h*DH;
    float* Sb = g_scores + (size_t)z*NQTOT*NKTOT;
    int tid = threadIdx.x;
    int bm = blockIdx.y<<6, bn = blockIdx.x<<6;
    int r = tid>>2, c = (tid&3)<<3;
    {
        float4 q0 = *(const float4*)(Qb + (size_t)(bm+r)*ADIM + c);
        float4 q1 = *(const float4*)(Qb + (size_t)(bm+r)*ADIM + c + 4);
        Qs[r][c  ]=q0.x; Qs[r][c+1]=q0.y; Qs[r][c+2]=q0.z; Qs[r][c+3]=q0.w;
        Qs[r][c+4]=q1.x; Qs[r][c+5]=q1.y; Qs[r][c+6]=q1.z; Qs[r][c+7]=q1.w;
        float4 k0v = *(const float4*)(Kb + (size_t)(bn+r)*ADIM + c);
        float4 k1v = *(const float4*)(Kb + (size_t)(bn+r)*ADIM + c + 4);
        Ks[r][c  ]=k0v.x; Ks[r][c+1]=k0v.y; Ks[r][c+2]=k0v.z; Ks[r][c+3]=k0v.w;
        Ks[r][c+4]=k1v.x; Ks[r][c+5]=k1v.y; Ks[r][c+6]=k1v.z; Ks[r][c+7]=k1v.w;
    }
    __syncthreads();
    int tx = tid&15, ty = tid>>4;
    float acc[4][4];
    #pragma unroll
    for(int i=0;i<4;i++)
        #pragma unroll
        for(int j=0;j<4;j++) acc[i][j]=0.f;
    #pragma unroll
    for(int kk=0;kk<32;kk++){
        float a[4], bq[4];
        #pragma unroll
        for(int i=0;i<4;i++) a[i]=Qs[(ty<<2)+i][kk];
        #pragma unroll
        for(int j=0;j<4;j++) bq[j]=Ks[(tx<<2)+j][kk];
        #pragma unroll
        for(int i=0;i<4;i++)
            #pragma unroll
            for(int j=0;j<4;j++) acc[i][j] += a[i]*bq[j];
    }
    const float scale = 0.17677669529663689f; // 1/sqrt(32)
    #pragma unroll
    for(int i=0;i<4;i++)
        #pragma unroll
        for(int j=0;j<4;j++)
            Sb[(size_t)(bm+(ty<<2)+i)*NKTOT + bn + (tx<<2) + j] = acc[i][j]*scale;
}

// ---------------- row softmax over 2240 keys ----------------
__global__ void k_softmax()
{
    __shared__ float buf[NKTOT];
    __shared__ float red[256];
    float* p = g_scores + (size_t)blockIdx.x*NKTOT;
    int tid = threadIdx.x;
    float m = -1e30f;
    for (int i=tid;i<NKTOT;i+=256){ float x=p[i]; buf[i]=x; m=fmaxf(m,x); }
    red[tid]=m; __syncthreads();
    for (int o=128;o>0;o>>=1){ if(tid<o) red[tid]=fmaxf(red[tid],red[tid+o]); __syncthreads(); }
    m = red[0]; __syncthreads();
    float s = 0.f;
    for (int i=tid;i<NKTOT;i+=256){ float e=__expf(buf[i]-m); buf[i]=e; s+=e; }
    red[tid]=s; __syncthreads();
    for (int o=128;o>0;o>>=1){ if(tid<o) red[tid]+=red[tid+o]; __syncthreads(); }
    float inv = 1.0f/red[0];
    for (int i=tid;i<NKTOT;i+=256) p[i]=buf[i]*inv;
}

// ---------------- gather weighted -> NCHW 96-channel image ----------------
__global__ void k_assemble(const float* __restrict__ W, float* __restrict__ X,
                           int qh, int qw, int qoff, int total)
{
    int idx = blockIdx.x*blockDim.x + threadIdx.x;
    if (idx >= total) return;
    int x = idx % qw;
    int t = idx / qw;
    int y = t % qh; t /= qh;
    int ch = t % 96; int b = t / 96;
    int hd = ch/12; int r2 = ch%12; int seg = r2>>2; int c = r2&3;
    int py=y>>3, ph=y&7, px=x>>3, pw=x&7;
    int n = qoff + py*(qw>>3) + px;
    int d = ((ph<<3)+pw)*4 + c;
    X[idx] = W[ ((size_t)((b*3+seg)*HEADS + hd)*NQTOT + n)*VHD + d ];
}

// ---------------- mbconv expand: grouped 1x1 (96->384, groups 8) + gelu ----------------
__global__ void k_expand(const float* __restrict__ X, const float* __restrict__ w,
                         const float* __restrict__ bias, float* __restrict__ H, int npix)
{
    __shared__ float ws[384*12];
    __shared__ float bs[384];
    int tid = threadIdx.x;
    for (int i=tid;i<4608;i+=256) ws[i]=w[i];
    for (int i=tid;i<384;i+=256) bs[i]=bias[i];
    __syncthreads();
    int pix = blockIdx.x*32 + (tid&31);
    int g = tid>>5;
    int b = blockIdx.y;
    const float* xin = X + ((size_t)b*96 + g*12)*npix + pix;
    float iv[12];
    #pragma unroll
    for (int i=0;i<12;i++) iv[i]=xin[(size_t)i*npix];
    float* hout = H + ((size_t)b*384 + g*48)*npix + pix;
    #pragma unroll 4
    for (int o=0;o<48;o++){
        const float* wr = &ws[(g*48+o)*12];
        float s2 = 0.f;
        #pragma unroll
        for (int i=0;i<12;i++) s2 += iv[i]*wr[i];
        hout[(size_t)o*npix] = gelu_f(s2 + bs[g*48+o]);
    }
}

// ---------------- depthwise 7x7 SAME + gelu ----------------
__global__ void k_dw(const float* __restrict__ H, const float* __restrict__ w,
                     const float* __restrict__ bias, float* __restrict__ O, int Hh, int Ww)
{
    __shared__ float sm[14][39];
    __shared__ float ws[49];
    int bz = blockIdx.z; int ch = bz % 384; int b = bz / 384;
    const float* in = H + ((size_t)(b*384)+ch)*Hh*Ww;
    int tx = threadIdx.x, ty = threadIdx.y; int tid = ty*32+tx;
    if (tid < 49) ws[tid] = w[ch*49 + tid];
    int bx = blockIdx.x*32, by = blockIdx.y*8;
    for (int i=tid;i<14*38;i+=256){
        int ly=i/38, lx=i%38;
        int gy=by+ly-3, gx=bx+lx-3;
        sm[ly][lx] = (gy>=0 && gy<Hh && gx>=0 && gx<Ww) ? in[(size_t)gy*Ww+gx] : 0.f;
    }
    __syncthreads();
    float s2 = 0.f;
    #pragma unroll
    for (int ky=0;ky<7;ky++)
        #pragma unroll
        for (int kx=0;kx<7;kx++)
            s2 += sm[ty+ky][tx+kx]*ws[ky*7+kx];
    O[((size_t)(b*384)+ch)*Hh*Ww + (size_t)(by+ty)*Ww + bx+tx] = gelu_f(s2 + bias[ch]);
}

// ---------------- mbconv proj: grouped 1x1 (384->32, groups 8) ----------------
__global__ void k_proj(const float* __restrict__ H, const float* __restrict__ w,
                       const float* __restrict__ bias, float* __restrict__ O, int npix)
{
    __shared__ float ws[32*48];
    int tid = threadIdx.x;
    for (int i=tid;i<1536;i+=256) ws[i]=w[i];
    __syncthreads();
    int pix = blockIdx.x*32 + (tid&31);
    int g = tid>>5;
    int b = blockIdx.y;
    const float* hin = H + ((size_t)b*384 + g*48)*npix + pix;
    float iv[48];
    #pragma unroll
    for (int i=0;i<48;i++) iv[i]=hin[(size_t)i*npix];
    #pragma unroll
    for (int o=0;o<4;o++){
        int oc = g*4 + o;
        const float* wr = &ws[oc*48];
        float s2 = 0.f;
        #pragma unroll
        for (int i=0;i<48;i++) s2 += iv[i]*wr[i];
        O[((size_t)b*32 + oc)*npix + pix] = s2 + bias[oc];
    }
}

// ---------------- host launch ----------------
#define GETSYM(p, sym) do { cudaGetSymbolAddress((void**)&(p), sym); } while(0)

extern "C" void kernel_launch(void* const* d_in, const int* in_sizes, int n_in,
                              void* d_out, int out_size)
{
    // Disambiguate input ordering: dict order has values_0 (4194304) at index 1,
    // signature order has keys_1 (1966080) there.
    bool dictOrder = (in_sizes[1] == 4194304);
    const float* K0 = (const float*)d_in[0];
    const float* V0 = (const float*)d_in[dictOrder ? 1 : 3];
    const float* K1 = (const float*)d_in[dictOrder ? 2 : 1];
    const float* V1 = (const float*)d_in[dictOrder ? 3 : 4];
    const float* K2 = (const float*)d_in[dictOrder ? 4 : 2];
    const float* V2 = (const float*)d_in[5];
    const float* Q0 = (const float*)d_in[6];
    const float* Q1 = (const float*)d_in[7];
    const float* LNG  = (const float*)d_in[8];
    const float* LNB  = (const float*)d_in[9];
    const float* KW1  = (const float*)d_in[10];
    const float* KB1  = (const float*)d_in[11];
    const float* KW2  = (const float*)d_in[12];
    const float* KB2  = (const float*)d_in[13];
    const float* QW1  = (const float*)d_in[14];
    const float* QB1  = (const float*)d_in[15];
    const float* QW2  = (const float*)d_in[16];
    const float* QB2  = (const float*)d_in[17];
    const float* WEXP = (const float*)d_in[18];
    const float* BEXP = (const float*)d_in[19];
    const float* WDW  = (const float*)d_in[20];
    const float* BDW  = (const float*)d_in[21];
    const float* WPRJ = (const float*)d_in[22];
    const float* BPRJ = (const float*)d_in[23];
    float* out = (float*)d_out;

    float *kseq, *vseq, *qseq, *khid, *kemb, *qhid, *qemb, *x0, *x1, *hid1, *hid2, *wtd;
    GETSYM(kseq, g_kseq); GETSYM(vseq, g_vseq); GETSYM(qseq, g_qseq);
    GETSYM(khid, g_khid); GETSYM(kemb, g_kemb);
    GETSYM(qhid, g_qhid); GETSYM(qemb, g_qemb);
    GETSYM(x0, g_x0); GETSYM(x1, g_x1);
    GETSYM(hid1, g_hid1); GETSYM(hid2, g_hid2);
    GETSYM(wtd, g_weighted);

    // 1) patchify
    k_patchify<<<2097152/256,256>>>(K0, kseq, 16,256,256,    0, NKTOT, KPD, 2097152);
    k_patchify<<<1966080/256,256>>>(K1, kseq, 16,192,320, 1024, NKTOT, KPD, 1966080);
    k_patchify<<< 524288/256,256>>>(K2, kseq, 16,128,128, 1984, NKTOT, KPD,  524288);
    k_patchify<<<4194304/256,256>>>(V0, vseq, 32,256,256,    0, NKTOT, VPD, 4194304);
    k_patchify<<<3932160/256,256>>>(V1, vseq, 32,192,320, 1024, NKTOT, VPD, 3932160);
    k_patchify<<<1048576/256,256>>>(V2, vseq, 32,128,128, 1984, NKTOT, VPD, 1048576);
    k_patchify<<<2097152/256,256>>>(Q0, qseq, 16,256,256,    0, NQTOT, QPD, 2097152);
    k_patchify<<<1179648/256,256>>>(Q1, qseq, 16,192,192, 1024, NQTOT, QPD, 1179648);

    // 2) layernorm values
    k_layernorm<<<BB*NKTOT,256>>>(vseq, LNG, LNB, VPD);

    // 3) embeddings (gelu MLP)
    k_gemm<<<dim3(ADIM/64, BB*NKTOT/64),256>>>(kseq, KPD, KW1, ADIM, KB1, khid, ADIM, KPD, 1);
    k_gemm<<<dim3(ADIM/64, BB*NKTOT/64),256>>>(khid, ADIM, KW2, ADIM, KB2, kemb, ADIM, ADIM, 0);
    k_gemm<<<dim3(ADIM/64, BB*NQTOT/64),256>>>(qseq, QPD, QW1, ADIM, QB1, qhid, ADIM, QPD, 1);
    k_gemm<<<dim3(ADIM/64, BB*NQTOT/64),256>>>(qhid, ADIM, QW2, ADIM, QB2, qemb, ADIM, ADIM, 0);

    // 4) attention
    k_qk<<<dim3(NKTOT/64, NQTOT/64, BB*HEADS),256>>>();
    k_softmax<<<BB*HEADS*NQTOT,256>>>();
    k_av<<<dim3(VHD/64, NQTOT/64, BB*3*HEADS),256>>>();

    // 5) assemble conv inputs
    k_assemble<<<12582912/256,256>>>(wtd, x0, 256,256,    0, 12582912);
    k_assemble<<< 7077888/256,256>>>(wtd, x1, 192,192, 1024,  7077888);

    // 6) mbconv image 0 (256x256)
    {
        int npix = 256*256;
        k_expand<<<dim3(npix/32, BB),256>>>(x0, WEXP, BEXP, hid1, npix);
        k_dw<<<dim3(256/32, 256/8, BB*384), dim3(32,8)>>>(hid1, WDW, BDW, hid2, 256, 256);
        k_proj<<<dim3(npix/32, BB),256>>>(hid2, WPRJ, BPRJ, out, npix);
    }
    // 7) mbconv image 1 (192x192)
    {
        int npix = 192*192;
        k_expand<<<dim3(npix/32, BB),256>>>(x1, WEXP, BEXP, hid1, npix);
        k_dw<<<dim3(192/32, 192/8, BB*384), dim3(32,8)>>>(hid1, WDW, BDW, hid2, 192, 192);
        k_proj<<<dim3(npix/32, BB),256>>>(hid2, WPRJ, BPRJ, out + (size_t)BB*32*256*256, npix);
    }
}

// round 3
// speedup vs baseline: 1.0881x; 1.0881x over previous
#include <cuda_runtime.h>
#include <cuda_bf16.h>
#include <math.h>

// ---------------- problem constants ----------------
#define BB 2
#define HEADS 8
#define DH 32
#define ADIM 256
#define NKTOT 2240          // 1024 + 960 + 256
#define NQTOT 1600          // 1024 + 576
#define KPD 1024            // 8*8*16
#define VPD 2048            // 8*8*32
#define QPD 1024
#define VHD 256             // VPD / HEADS

// ---------------- scratch buffers (static device allocs) ----------------
__device__ float g_kseq[BB*NKTOT*KPD];
__device__ float g_vseq[BB*NKTOT*VPD];
__device__ float g_qseq[BB*NQTOT*QPD];
__device__ float g_khid[BB*NKTOT*ADIM];
__device__ float g_kemb[BB*NKTOT*ADIM];
__device__ float g_qhid[BB*NQTOT*ADIM];
__device__ float g_qemb[BB*NQTOT*ADIM];
__device__ float g_scores[(size_t)BB*HEADS*NQTOT*NKTOT];
__device__ float g_weighted[(size_t)BB*3*HEADS*NQTOT*VHD];
__device__ float g_x0[BB*96*256*256];
__device__ float g_x1[BB*96*192*192];
__device__ float g_hid1[(size_t)BB*384*256*256];
__device__ float g_hid2[(size_t)BB*384*256*256];

__device__ __forceinline__ float gelu_f(float x){
    return 0.5f*x*(1.0f + tanhf(0.7978845608028654f*(x + 0.044715f*x*x*x)));
}

// ---------------- packed f32x2 helpers ----------------
__device__ __forceinline__ unsigned long long pk2(float lo, float hi){
    unsigned long long r; asm("mov.b64 %0, {%1, %2};" : "=l"(r) : "f"(lo), "f"(hi)); return r;
}
__device__ __forceinline__ void upk2(unsigned long long v, float& lo, float& hi){
    asm("mov.b64 {%0, %1}, %2;" : "=f"(lo), "=f"(hi) : "l"(v));
}
#define FFMA2(acc, a, b) asm("fma.rn.f32x2 %0, %1, %2, %3;" : "=l"(acc) : "l"(a), "l"(b), "l"(acc))

// ---------------- patchify: NCHW image -> [b, n, (ph,pw,c)] ----------------
__global__ void k_patchify(const float* __restrict__ src, float* __restrict__ dst,
                           int C, int Himg, int Wimg, int nOff, int Ntot, int featDim, int total)
{
    int idx = blockIdx.x*blockDim.x + threadIdx.x;
    if (idx >= total) return;
    int x = idx % Wimg;
    int t = idx / Wimg;
    int y = t % Himg; t /= Himg;
    int c = t % C;    int b = t / C;
    int hp = y>>3, ph = y&7, wp = x>>3, pw = x&7;
    int n = hp*(Wimg>>3) + wp;
    int f = ((ph<<3)+pw)*C + c;
    dst[(size_t)(b*Ntot + nOff + n)*featDim + f] = src[idx];
}

// ---------------- layernorm rows (in place) ----------------
__global__ void k_layernorm(float* __restrict__ v, const float* __restrict__ g,
                            const float* __restrict__ bta, int dim)
{
    float* p = v + (size_t)blockIdx.x*dim;
    __shared__ float red[256];
    int tid = threadIdx.x;
    float s=0.f, s2=0.f;
    for (int i=tid;i<dim;i+=256){ float x=p[i]; s+=x; s2+=x*x; }
    red[tid]=s; __syncthreads();
    for (int o=128;o>0;o>>=1){ if(tid<o) red[tid]+=red[tid+o]; __syncthreads(); }
    float mean = red[0]/dim; __syncthreads();
    red[tid]=s2; __syncthreads();
    for (int o=128;o>0;o>>=1){ if(tid<o) red[tid]+=red[tid+o]; __syncthreads(); }
    float var = red[0]/dim - mean*mean;
    float rstd = rsqrtf(var + 1e-5f);
    for (int i=tid;i<dim;i+=256){ float x=p[i]; p[i]=(x-mean)*rstd*g[i]+bta[i]; }
}

// ---------------- packed-FFMA2 tiled GEMM: 64x128 tile, BK=16, 128 thr, 8x8/thr --------
// C = act(A@B + bias). Requires M%64==0, N%128==0, K%16==0, rows 16B-aligned.
template<int ACT, bool HASBIAS>
__device__ __forceinline__ void gemm2_body(
    const float* __restrict__ A, int lda,
    const float* __restrict__ Bm, int ldb,
    const float* __restrict__ bias,
    float* __restrict__ C, int ldc,
    int K, int bm, int bn)
{
    __shared__ float As[16][68];    // k-major (transposed)
    __shared__ float Bs[16][128];
    int tid = threadIdx.x;
    int tx = tid & 15, ty = tid >> 4;         // tx: 16 col-groups of 8, ty: 8 row-groups of 8
    int ra = tid >> 1, ca = (tid & 1) << 3;   // A load: 64 rows x 16 k
    int rb = tid >> 3, cb = (tid & 7) << 4;   // B load: 16 rows x 128 n

    unsigned long long acc[8][4];
    #pragma unroll
    for (int i=0;i<8;i++)
        #pragma unroll
        for (int j=0;j<4;j++) acc[i][j] = 0ull;

    const float* Ap = A + (size_t)(bm + ra)*lda + ca;
    const float* Bp = Bm + (size_t)rb*ldb + bn + cb;

    for (int k0 = 0; k0 < K; k0 += 16){
        float4 a0 = *(const float4*)(Ap + k0);
        float4 a1 = *(const float4*)(Ap + k0 + 4);
        As[ca+0][ra]=a0.x; As[ca+1][ra]=a0.y; As[ca+2][ra]=a0.z; As[ca+3][ra]=a0.w;
        As[ca+4][ra]=a1.x; As[ca+5][ra]=a1.y; As[ca+6][ra]=a1.z; As[ca+7][ra]=a1.w;
        const float* bsrc = Bp + (size_t)k0*ldb;
        #pragma unroll
        for (int j=0;j<4;j++)
            *(float4*)&Bs[rb][cb + j*4] = *(const float4*)(bsrc + j*4);
        __syncthreads();

        #pragma unroll
        for (int kk=0; kk<16; kk++){
            float4 af0 = *(const float4*)&As[kk][ty<<3];
            float4 af1 = *(const float4*)&As[kk][(ty<<3)+4];
            unsigned long long a2[8];
            a2[0]=pk2(af0.x,af0.x); a2[1]=pk2(af0.y,af0.y);
            a2[2]=pk2(af0.z,af0.z); a2[3]=pk2(af0.w,af0.w);
            a2[4]=pk2(af1.x,af1.x); a2[5]=pk2(af1.y,af1.y);
            a2[6]=pk2(af1.z,af1.z); a2[7]=pk2(af1.w,af1.w);
            ulonglong2 bb0 = *(const ulonglong2*)&Bs[kk][tx<<3];
            ulonglong2 bb1 = *(const ulonglong2*)&Bs[kk][(tx<<3)+4];
            unsigned long long b2[4] = {bb0.x, bb0.y, bb1.x, bb1.y};
            #pragma unroll
            for (int i=0;i<8;i++)
                #pragma unroll
                for (int j=0;j<4;j++)
                    FFMA2(acc[i][j], a2[i], b2[j]);
        }
        __syncthreads();
    }

    #pragma unroll
    for (int i=0;i<8;i++){
        float vout[8];
        #pragma unroll
        for (int j=0;j<4;j++) upk2(acc[i][j], vout[2*j], vout[2*j+1]);
        if (HASBIAS){
            #pragma unroll
            for (int c=0;c<8;c++) vout[c] += bias[bn + (tx<<3) + c];
        }
        if (ACT){
            #pragma unroll
            for (int c=0;c<8;c++) vout[c] = gelu_f(vout[c]);
        }
        float* cp = C + (size_t)(bm + (ty<<3) + i)*ldc + bn + (tx<<3);
        *(float4*)cp     = make_float4(vout[0],vout[1],vout[2],vout[3]);
        *(float4*)(cp+4) = make_float4(vout[4],vout[5],vout[6],vout[7]);
    }
}

template<int ACT, bool HASBIAS>
__global__ __launch_bounds__(128) void k_gemm2(
    const float* __restrict__ A, int lda,
    const float* __restrict__ Bm, int ldb,
    const float* __restrict__ bias,
    float* __restrict__ C, int ldc, int K)
{
    gemm2_body<ACT,HASBIAS>(A, lda, Bm, ldb, bias, C, ldc, K, blockIdx.y<<6, blockIdx.x<<7);
}

// ---------------- A*V per (b, seg, head) ----------------
__global__ __launch_bounds__(128) void k_av2()
{
    int z = blockIdx.z;
    int h = z & 7; int t = z >> 3; int seg = t % 3; int b = t / 3;
    const int segOff[3] = {0, 1024, 1984};
    const int segN[3]   = {1024, 960, 256};
    const float* A = g_scores + (size_t)(b*HEADS + h)*NQTOT*NKTOT + segOff[seg];
    const float* Bv = g_vseq + ((size_t)b*NKTOT + segOff[seg])*VPD + h*VHD;
    float* C = g_weighted + (size_t)((b*3 + seg)*HEADS + h)*NQTOT*VHD;
    gemm2_body<0,false>(A, NKTOT, Bv, VPD, nullptr, C, VHD, segN[seg], blockIdx.y<<6, blockIdx.x<<7);
}

// ---------------- Q @ K^T (d=32), 64x64 tile, packed FFMA2 ----------------
__global__ __launch_bounds__(128) void k_qk2()
{
    __shared__ float Qs[32][68];   // k-major
    __shared__ float Ks[32][68];   // k-major (i.e. K^T ready)
    int z = blockIdx.z; int b = z>>3, h = z&7;
    const float* Qb = g_qemb + (size_t)b*NQTOT*ADIM + h*DH;
    const float* Kb = g_kemb + (size_t)b*NKTOT*ADIM + h*DH;
    float* Sb = g_scores + (size_t)z*NQTOT*NKTOT;
    int tid = threadIdx.x;
    int bm = blockIdx.y<<6, bn = blockIdx.x<<6;
    int ra = tid>>1, ca = (tid&1)<<4;
    #pragma unroll
    for (int j=0;j<4;j++){
        float4 q = *(const float4*)(Qb + (size_t)(bm+ra)*ADIM + ca + j*4);
        Qs[ca+j*4+0][ra]=q.x; Qs[ca+j*4+1][ra]=q.y; Qs[ca+j*4+2][ra]=q.z; Qs[ca+j*4+3][ra]=q.w;
        float4 kv = *(const float4*)(Kb + (size_t)(bn+ra)*ADIM + ca + j*4);
        Ks[ca+j*4+0][ra]=kv.x; Ks[ca+j*4+1][ra]=kv.y; Ks[ca+j*4+2][ra]=kv.z; Ks[ca+j*4+3][ra]=kv.w;
    }
    __syncthreads();
    int tx = tid&15, ty = tid>>4;     // tx: 16 col-groups of 4, ty: 8 row-groups of 8
    unsigned long long acc[8][2];
    #pragma unroll
    for (int i=0;i<8;i++){ acc[i][0]=0ull; acc[i][1]=0ull; }
    #pragma unroll
    for (int kk=0; kk<32; kk++){
        float4 af0 = *(const float4*)&Qs[kk][ty<<3];
        float4 af1 = *(const float4*)&Qs[kk][(ty<<3)+4];
        unsigned long long a2[8];
        a2[0]=pk2(af0.x,af0.x); a2[1]=pk2(af0.y,af0.y);
        a2[2]=pk2(af0.z,af0.z); a2[3]=pk2(af0.w,af0.w);
        a2[4]=pk2(af1.x,af1.x); a2[5]=pk2(af1.y,af1.y);
        a2[6]=pk2(af1.z,af1.z); a2[7]=pk2(af1.w,af1.w);
        ulonglong2 bb = *(const ulonglong2*)&Ks[kk][tx<<2];
        #pragma unroll
        for (int i=0;i<8;i++){
            FFMA2(acc[i][0], a2[i], bb.x);
            FFMA2(acc[i][1], a2[i], bb.y);
        }
    }
    const float scale = 0.17677669529663689f; // 1/sqrt(32)
    #pragma unroll
    for (int i=0;i<8;i++){
        float v0,v1,v2,v3;
        upk2(acc[i][0], v0, v1);
        upk2(acc[i][1], v2, v3);
        float* cp = Sb + (size_t)(bm+(ty<<3)+i)*NKTOT + bn + (tx<<2);
        *(float4*)cp = make_float4(v0*scale, v1*scale, v2*scale, v3*scale);
    }
}

// ---------------- row softmax over 2240 keys ----------------
__global__ void k_softmax()
{
    __shared__ float buf[NKTOT];
    __shared__ float red[256];
    float* p = g_scores + (size_t)blockIdx.x*NKTOT;
    int tid = threadIdx.x;
    float m = -1e30f;
    for (int i=tid;i<NKTOT;i+=256){ float x=p[i]; buf[i]=x; m=fmaxf(m,x); }
    red[tid]=m; __syncthreads();
    for (int o=128;o>0;o>>=1){ if(tid<o) red[tid]=fmaxf(red[tid],red[tid+o]); __syncthreads(); }
    m = red[0]; __syncthreads();
    float s = 0.f;
    for (int i=tid;i<NKTOT;i+=256){ float e=__expf(buf[i]-m); buf[i]=e; s+=e; }
    red[tid]=s; __syncthreads();
    for (int o=128;o>0;o>>=1){ if(tid<o) red[tid]+=red[tid+o]; __syncthreads(); }
    float inv = 1.0f/red[0];
    for (int i=tid;i<NKTOT;i+=256) p[i]=buf[i]*inv;
}

// ---------------- gather weighted -> NCHW 96-channel image ----------------
__global__ void k_assemble(const float* __restrict__ W, float* __restrict__ X,
                           int qh, int qw, int qoff, int total)
{
    int idx = blockIdx.x*blockDim.x + threadIdx.x;
    if (idx >= total) return;
    int x = idx % qw;
    int t = idx / qw;
    int y = t % qh; t /= qh;
    int ch = t % 96; int b = t / 96;
    int hd = ch/12; int r2 = ch%12; int seg = r2>>2; int c = r2&3;
    int py=y>>3, ph=y&7, px=x>>3, pw=x&7;
    int n = qoff + py*(qw>>3) + px;
    int d = ((ph<<3)+pw)*4 + c;
    X[idx] = W[ ((size_t)((b*3+seg)*HEADS + hd)*NQTOT + n)*VHD + d ];
}

// ---------------- mbconv expand: grouped 1x1 (96->384, groups 8) + gelu ----------------
__global__ void k_expand(const float* __restrict__ X, const float* __restrict__ w,
                         const float* __restrict__ bias, float* __restrict__ H, int npix)
{
    __shared__ float ws[384*12];
    __shared__ float bs[384];
    int tid = threadIdx.x;
    for (int i=tid;i<4608;i+=256) ws[i]=w[i];
    for (int i=tid;i<384;i+=256) bs[i]=bias[i];
    __syncthreads();
    int pix = blockIdx.x*32 + (tid&31);
    int g = tid>>5;
    int b = blockIdx.y;
    const float* xin = X + ((size_t)b*96 + g*12)*npix + pix;
    float iv[12];
    #pragma unroll
    for (int i=0;i<12;i++) iv[i]=xin[(size_t)i*npix];
    float* hout = H + ((size_t)b*384 + g*48)*npix + pix;
    #pragma unroll 4
    for (int o=0;o<48;o++){
        const float* wr = &ws[(g*48+o)*12];
        float s2 = 0.f;
        #pragma unroll
        for (int i=0;i<12;i++) s2 += iv[i]*wr[i];
        hout[(size_t)o*npix] = gelu_f(s2 + bs[g*48+o]);
    }
}

// ---------------- depthwise 7x7 SAME + gelu ----------------
__global__ void k_dw(const float* __restrict__ H, const float* __restrict__ w,
                     const float* __restrict__ bias, float* __restrict__ O, int Hh, int Ww)
{
    __shared__ float sm[14][39];
    __shared__ float ws[49];
    int bz = blockIdx.z; int ch = bz % 384; int b = bz / 384;
    const float* in = H + ((size_t)(b*384)+ch)*Hh*Ww;
    int tx = threadIdx.x, ty = threadIdx.y; int tid = ty*32+tx;
    if (tid < 49) ws[tid] = w[ch*49 + tid];
    int bx = blockIdx.x*32, by = blockIdx.y*8;
    for (int i=tid;i<14*38;i+=256){
        int ly=i/38, lx=i%38;
        int gy=by+ly-3, gx=bx+lx-3;
        sm[ly][lx] = (gy>=0 && gy<Hh && gx>=0 && gx<Ww) ? in[(size_t)gy*Ww+gx] : 0.f;
    }
    __syncthreads();
    float s2 = 0.f;
    #pragma unroll
    for (int ky=0;ky<7;ky++)
        #pragma unroll
        for (int kx=0;kx<7;kx++)
            s2 += sm[ty+ky][tx+kx]*ws[ky*7+kx];
    O[((size_t)(b*384)+ch)*Hh*Ww + (size_t)(by+ty)*Ww + bx+tx] = gelu_f(s2 + bias[ch]);
}

// ---------------- mbconv proj: grouped 1x1 (384->32, groups 8) ----------------
__global__ void k_proj(const float* __restrict__ H, const float* __restrict__ w,
                       const float* __restrict__ bias, float* __restrict__ O, int npix)
{
    __shared__ float ws[32*48];
    int tid = threadIdx.x;
    for (int i=tid;i<1536;i+=256) ws[i]=w[i];
    __syncthreads();
    int pix = blockIdx.x*32 + (tid&31);
    int g = tid>>5;
    int b = blockIdx.y;
    const float* hin = H + ((size_t)b*384 + g*48)*npix + pix;
    float iv[48];
    #pragma unroll
    for (int i=0;i<48;i++) iv[i]=hin[(size_t)i*npix];
    #pragma unroll
    for (int o=0;o<4;o++){
        int oc = g*4 + o;
        const float* wr = &ws[oc*48];
        float s2 = 0.f;
        #pragma unroll
        for (int i=0;i<48;i++) s2 += iv[i]*wr[i];
        O[((size_t)b*32 + oc)*npix + pix] = s2 + bias[oc];
    }
}

// ---------------- host launch ----------------
#define GETSYM(p, sym) do { cudaGetSymbolAddress((void**)&(p), sym); } while(0)

extern "C" void kernel_launch(void* const* d_in, const int* in_sizes, int n_in,
                              void* d_out, int out_size)
{
    bool dictOrder = (in_sizes[1] == 4194304);
    const float* K0 = (const float*)d_in[0];
    const float* V0 = (const float*)d_in[dictOrder ? 1 : 3];
    const float* K1 = (const float*)d_in[dictOrder ? 2 : 1];
    const float* V1 = (const float*)d_in[dictOrder ? 3 : 4];
    const float* K2 = (const float*)d_in[dictOrder ? 4 : 2];
    const float* V2 = (const float*)d_in[5];
    const float* Q0 = (const float*)d_in[6];
    const float* Q1 = (const float*)d_in[7];
    const float* LNG  = (const float*)d_in[8];
    const float* LNB  = (const float*)d_in[9];
    const float* KW1  = (const float*)d_in[10];
    const float* KB1  = (const float*)d_in[11];
    const float* KW2  = (const float*)d_in[12];
    const float* KB2  = (const float*)d_in[13];
    const float* QW1  = (const float*)d_in[14];
    const float* QB1  = (const float*)d_in[15];
    const float* QW2  = (const float*)d_in[16];
    const float* QB2  = (const float*)d_in[17];
    const float* WEXP = (const float*)d_in[18];
    const float* BEXP = (const float*)d_in[19];
    const float* WDW  = (const float*)d_in[20];
    const float* BDW  = (const float*)d_in[21];
    const float* WPRJ = (const float*)d_in[22];
    const float* BPRJ = (const float*)d_in[23];
    float* out = (float*)d_out;

    float *kseq, *vseq, *qseq, *khid, *kemb, *qhid, *qemb, *x0, *x1, *hid1, *hid2, *wtd;
    GETSYM(kseq, g_kseq); GETSYM(vseq, g_vseq); GETSYM(qseq, g_qseq);
    GETSYM(khid, g_khid); GETSYM(kemb, g_kemb);
    GETSYM(qhid, g_qhid); GETSYM(qemb, g_qemb);
    GETSYM(x0, g_x0); GETSYM(x1, g_x1);
    GETSYM(hid1, g_hid1); GETSYM(hid2, g_hid2);
    GETSYM(wtd, g_weighted);

    // 1) patchify
    k_patchify<<<2097152/256,256>>>(K0, kseq, 16,256,256,    0, NKTOT, KPD, 2097152);
    k_patchify<<<1966080/256,256>>>(K1, kseq, 16,192,320, 1024, NKTOT, KPD, 1966080);
    k_patchify<<< 524288/256,256>>>(K2, kseq, 16,128,128, 1984, NKTOT, KPD,  524288);
    k_patchify<<<4194304/256,256>>>(V0, vseq, 32,256,256,    0, NKTOT, VPD, 4194304);
    k_patchify<<<3932160/256,256>>>(V1, vseq, 32,192,320, 1024, NKTOT, VPD, 3932160);
    k_patchify<<<1048576/256,256>>>(V2, vseq, 32,128,128, 1984, NKTOT, VPD, 1048576);
    k_patchify<<<2097152/256,256>>>(Q0, qseq, 16,256,256,    0, NQTOT, QPD, 2097152);
    k_patchify<<<1179648/256,256>>>(Q1, qseq, 16,192,192, 1024, NQTOT, QPD, 1179648);

    // 2) layernorm values
    k_layernorm<<<BB*NKTOT,256>>>(vseq, LNG, LNB, VPD);

    // 3) embeddings (gelu MLP), packed-FFMA2 GEMMs
    k_gemm2<1,true><<<dim3(ADIM/128, BB*NKTOT/64),128>>>(kseq, KPD, KW1, ADIM, KB1, khid, ADIM, KPD);
    k_gemm2<0,true><<<dim3(ADIM/128, BB*NKTOT/64),128>>>(khid, ADIM, KW2, ADIM, KB2, kemb, ADIM, ADIM);
    k_gemm2<1,true><<<dim3(ADIM/128, BB*NQTOT/64),128>>>(qseq, QPD, QW1, ADIM, QB1, qhid, ADIM, QPD);
    k_gemm2<0,true><<<dim3(ADIM/128, BB*NQTOT/64),128>>>(qhid, ADIM, QW2, ADIM, QB2, qemb, ADIM, ADIM);

    // 4) attention
    k_qk2<<<dim3(NKTOT/64, NQTOT/64, BB*HEADS),128>>>();
    k_softmax<<<BB*HEADS*NQTOT,256>>>();
    k_av2<<<dim3(VHD/128, NQTOT/64, BB*3*HEADS),128>>>();

    // 5) assemble conv inputs
    k_assemble<<<12582912/256,256>>>(wtd, x0, 256,256,    0, 12582912);
    k_assemble<<< 7077888/256,256>>>(wtd, x1, 192,192, 1024,  7077888);

    // 6) mbconv image 0 (256x256)
    {
        int npix = 256*256;
        k_expand<<<dim3(npix/32, BB),256>>>(x0, WEXP, BEXP, hid1, npix);
        k_dw<<<dim3(256/32, 256/8, BB*384), dim3(32,8)>>>(hid1, WDW, BDW, hid2, 256, 256);
        k_proj<<<dim3(npix/32, BB),256>>>(hid2, WPRJ, BPRJ, out, npix);
    }
    // 7) mbconv image 1 (192x192)
    {
        int npix = 192*192;
        k_expand<<<dim3(npix/32, BB),256>>>(x1, WEXP, BEXP, hid1, npix);
        k_dw<<<dim3(192/32, 192/8, BB*384), dim3(32,8)>>>(hid1, WDW, BDW, hid2, 192, 192);
        k_proj<<<dim3(npix/32, BB),256>>>(hid2, WPRJ, BPRJ, out + (size_t)BB*32*256*256, npix);
    }
}

// round 4
// speedup vs baseline: 1.1649x; 1.0706x over previous
#include <cuda_runtime.h>
#include <cuda_bf16.h>
#include <math.h>

// ---------------- problem constants ----------------
#define BB 2
#define HEADS 8
#define DH 32
#define ADIM 256
#define NKTOT 2240          // 1024 + 960 + 256
#define NQTOT 1600          // 1024 + 576
#define KPD 1024            // 8*8*16
#define VPD 2048            // 8*8*32
#define QPD 1024
#define VHD 256             // VPD / HEADS

// ---------------- scratch buffers (static device allocs) ----------------
__device__ float g_kseq[BB*NKTOT*KPD];
__device__ float g_vseq[BB*NKTOT*VPD];
__device__ float g_qseq[BB*NQTOT*QPD];
__device__ float g_khid[BB*NKTOT*ADIM];
__device__ float g_kemb[BB*NKTOT*ADIM];
__device__ float g_qhid[BB*NQTOT*ADIM];
__device__ float g_qemb[BB*NQTOT*ADIM];
__device__ float g_scores[(size_t)BB*HEADS*NQTOT*NKTOT];
__device__ float g_weighted[(size_t)BB*3*HEADS*NQTOT*VHD];
__device__ float g_x0[BB*96*256*256];
__device__ float g_x1[BB*96*192*192];
__device__ float g_hid1[(size_t)BB*384*256*256];
__device__ float g_hid2[(size_t)BB*384*256*256];

__device__ __forceinline__ float gelu_f(float x){
    return 0.5f*x*(1.0f + tanhf(0.7978845608028654f*(x + 0.044715f*x*x*x)));
}

// ---------------- packed f32x2 helpers ----------------
__device__ __forceinline__ unsigned long long pk2(float lo, float hi){
    unsigned long long r; asm("mov.b64 %0, {%1, %2};" : "=l"(r) : "f"(lo), "f"(hi)); return r;
}
__device__ __forceinline__ void upk2(unsigned long long v, float& lo, float& hi){
    asm("mov.b64 {%0, %1}, %2;" : "=f"(lo), "=f"(hi) : "l"(v));
}
#define FFMA2(acc, a, b) asm("fma.rn.f32x2 %0, %1, %2, %3;" : "=l"(acc) : "l"(a), "l"(b), "l"(acc))

// ---------------- merged patchify: all 8 images in one launch ----------------
// NCHW image -> [b, n, (ph,pw,c)] rows. Hardcoded shape table.
__global__ void k_patchify_all(
    const float* __restrict__ K0, const float* __restrict__ K1, const float* __restrict__ K2,
    const float* __restrict__ V0, const float* __restrict__ V1, const float* __restrict__ V2,
    const float* __restrict__ Q0, const float* __restrict__ Q1,
    float* __restrict__ kseq, float* __restrict__ vseq, float* __restrict__ qseq)
{
    long gidx = (long)blockIdx.x*blockDim.x + threadIdx.x;  // < 17039360 exactly
    const float* src; float* dst;
    int C, Hh, Ww, nOff, Ntot, fd; long base;
    if      (gidx <  2097152){ src=K0; dst=kseq; C=16; Hh=256; Ww=256; nOff=0;    Ntot=NKTOT; fd=KPD; base=0; }
    else if (gidx <  4063232){ src=K1; dst=kseq; C=16; Hh=192; Ww=320; nOff=1024; Ntot=NKTOT; fd=KPD; base=2097152; }
    else if (gidx <  4587520){ src=K2; dst=kseq; C=16; Hh=128; Ww=128; nOff=1984; Ntot=NKTOT; fd=KPD; base=4063232; }
    else if (gidx <  8781824){ src=V0; dst=vseq; C=32; Hh=256; Ww=256; nOff=0;    Ntot=NKTOT; fd=VPD; base=4587520; }
    else if (gidx < 12713984){ src=V1; dst=vseq; C=32; Hh=192; Ww=320; nOff=1024; Ntot=NKTOT; fd=VPD; base=8781824; }
    else if (gidx < 13762560){ src=V2; dst=vseq; C=32; Hh=128; Ww=128; nOff=1984; Ntot=NKTOT; fd=VPD; base=12713984; }
    else if (gidx < 15859712){ src=Q0; dst=qseq; C=16; Hh=256; Ww=256; nOff=0;    Ntot=NQTOT; fd=QPD; base=13762560; }
    else                     { src=Q0; dst=qseq; C=16; Hh=192; Ww=192; nOff=1024; Ntot=NQTOT; fd=QPD; base=15859712; src=Q1; }
    long idx = gidx - base;
    int x = (int)(idx % Ww);
    long t = idx / Ww;
    int y = (int)(t % Hh); t /= Hh;
    int c = (int)(t % C);  int b = (int)(t / C);
    int hp = y>>3, ph = y&7, wp = x>>3, pw = x&7;
    int n = hp*(Ww>>3) + wp;
    int f = ((ph<<3)+pw)*C + c;
    dst[(size_t)(b*Ntot + nOff + n)*fd + f] = src[idx];
}

// ---------------- layernorm rows (in place) ----------------
__global__ void k_layernorm(float* __restrict__ v, const float* __restrict__ g,
                            const float* __restrict__ bta, int dim)
{
    float* p = v + (size_t)blockIdx.x*dim;
    __shared__ float red[256];
    int tid = threadIdx.x;
    float s=0.f, s2=0.f;
    for (int i=tid;i<dim;i+=256){ float x=p[i]; s+=x; s2+=x*x; }
    red[tid]=s; __syncthreads();
    for (int o=128;o>0;o>>=1){ if(tid<o) red[tid]+=red[tid+o]; __syncthreads(); }
    float mean = red[0]/dim; __syncthreads();
    red[tid]=s2; __syncthreads();
    for (int o=128;o>0;o>>=1){ if(tid<o) red[tid]+=red[tid+o]; __syncthreads(); }
    float var = red[0]/dim - mean*mean;
    float rstd = rsqrtf(var + 1e-5f);
    for (int i=tid;i<dim;i+=256){ float x=p[i]; p[i]=(x-mean)*rstd*g[i]+bta[i]; }
}

// ------- double-buffered packed-FFMA2 GEMM: 64x128 tile, BK=16, 128 thr, 8x8/thr -------
// C = act(A@B + bias). Requires M%64==0, N%128==0, K%16==0, rows 16B-aligned.
template<int ACT, bool HASBIAS>
__device__ __forceinline__ void gemm3_body(
    const float* __restrict__ A, int lda,
    const float* __restrict__ Bm, int ldb,
    const float* __restrict__ bias,
    float* __restrict__ C, int ldc,
    int K, int bm, int bn)
{
    __shared__ float As[2][16][68];    // k-major (transposed)
    __shared__ float Bs[2][16][128];
    int tid = threadIdx.x;
    int tx = tid & 15, ty = tid >> 4;
    int ra = tid >> 1, ca = (tid & 1) << 3;   // A load: 64 rows x 16 k
    int rb = tid >> 3, cb = (tid & 7) << 4;   // B load: 16 rows x 128 n

    unsigned long long acc[8][4];
    #pragma unroll
    for (int i=0;i<8;i++)
        #pragma unroll
        for (int j=0;j<4;j++) acc[i][j] = 0ull;

    const float* Ap = A + (size_t)(bm + ra)*lda + ca;
    const float* Bp = Bm + (size_t)rb*ldb + bn + cb;

    // prologue: tile 0 -> buf 0
    {
        float4 a0 = *(const float4*)(Ap);
        float4 a1 = *(const float4*)(Ap + 4);
        As[0][ca+0][ra]=a0.x; As[0][ca+1][ra]=a0.y; As[0][ca+2][ra]=a0.z; As[0][ca+3][ra]=a0.w;
        As[0][ca+4][ra]=a1.x; As[0][ca+5][ra]=a1.y; As[0][ca+6][ra]=a1.z; As[0][ca+7][ra]=a1.w;
        #pragma unroll
        for (int j=0;j<4;j++)
            *(float4*)&Bs[0][rb][cb + j*4] = *(const float4*)(Bp + j*4);
    }
    __syncthreads();

    int buf = 0;
    for (int k0 = 0; k0 < K; k0 += 16){
        bool hasNext = (k0 + 16 < K);
        float4 na0, na1, nb0, nb1, nb2, nb3;
        if (hasNext){
            na0 = *(const float4*)(Ap + k0 + 16);
            na1 = *(const float4*)(Ap + k0 + 20);
            const float* bsrc = Bp + (size_t)(k0+16)*ldb;
            nb0 = *(const float4*)(bsrc);
            nb1 = *(const float4*)(bsrc + 4);
            nb2 = *(const float4*)(bsrc + 8);
            nb3 = *(const float4*)(bsrc + 12);
        }
        #pragma unroll
        for (int kk=0; kk<16; kk++){
            float4 af0 = *(const float4*)&As[buf][kk][ty<<3];
            float4 af1 = *(const float4*)&As[buf][kk][(ty<<3)+4];
            unsigned long long a2[8];
            a2[0]=pk2(af0.x,af0.x); a2[1]=pk2(af0.y,af0.y);
            a2[2]=pk2(af0.z,af0.z); a2[3]=pk2(af0.w,af0.w);
            a2[4]=pk2(af1.x,af1.x); a2[5]=pk2(af1.y,af1.y);
            a2[6]=pk2(af1.z,af1.z); a2[7]=pk2(af1.w,af1.w);
            ulonglong2 bb0 = *(const ulonglong2*)&Bs[buf][kk][tx<<3];
            ulonglong2 bb1 = *(const ulonglong2*)&Bs[buf][kk][(tx<<3)+4];
            unsigned long long b2[4] = {bb0.x, bb0.y, bb1.x, bb1.y};
            #pragma unroll
            for (int i=0;i<8;i++)
                #pragma unroll
                for (int j=0;j<4;j++)
                    FFMA2(acc[i][j], a2[i], b2[j]);
        }
        if (hasNext){
            int nbuf = buf ^ 1;
            As[nbuf][ca+0][ra]=na0.x; As[nbuf][ca+1][ra]=na0.y;
            As[nbuf][ca+2][ra]=na0.z; As[nbuf][ca+3][ra]=na0.w;
            As[nbuf][ca+4][ra]=na1.x; As[nbuf][ca+5][ra]=na1.y;
            As[nbuf][ca+6][ra]=na1.z; As[nbuf][ca+7][ra]=na1.w;
            *(float4*)&Bs[nbuf][rb][cb   ] = nb0;
            *(float4*)&Bs[nbuf][rb][cb+ 4] = nb1;
            *(float4*)&Bs[nbuf][rb][cb+ 8] = nb2;
            *(float4*)&Bs[nbuf][rb][cb+12] = nb3;
            __syncthreads();
            buf = nbuf;
        }
    }

    #pragma unroll
    for (int i=0;i<8;i++){
        float vout[8];
        #pragma unroll
        for (int j=0;j<4;j++) upk2(acc[i][j], vout[2*j], vout[2*j+1]);
        if (HASBIAS){
            #pragma unroll
            for (int c=0;c<8;c++) vout[c] += bias[bn + (tx<<3) + c];
        }
        if (ACT){
            #pragma unroll
            for (int c=0;c<8;c++) vout[c] = gelu_f(vout[c]);
        }
        float* cp = C + (size_t)(bm + (ty<<3) + i)*ldc + bn + (tx<<3);
        *(float4*)cp     = make_float4(vout[0],vout[1],vout[2],vout[3]);
        *(float4*)(cp+4) = make_float4(vout[4],vout[5],vout[6],vout[7]);
    }
}

template<int ACT, bool HASBIAS>
__global__ __launch_bounds__(128,3) void k_gemm3(
    const float* __restrict__ A, int lda,
    const float* __restrict__ Bm, int ldb,
    const float* __restrict__ bias,
    float* __restrict__ C, int ldc, int K)
{
    gemm3_body<ACT,HASBIAS>(A, lda, Bm, ldb, bias, C, ldc, K, blockIdx.y<<6, blockIdx.x<<7);
}

// ---------------- A*V per (b, seg, head) ----------------
__global__ __launch_bounds__(128,3) void k_av3()
{
    int z = blockIdx.z;
    int h = z & 7; int t = z >> 3; int seg = t % 3; int b = t / 3;
    const int segOff[3] = {0, 1024, 1984};
    const int segN[3]   = {1024, 960, 256};
    const float* A = g_scores + (size_t)(b*HEADS + h)*NQTOT*NKTOT + segOff[seg];
    const float* Bv = g_vseq + ((size_t)b*NKTOT + segOff[seg])*VPD + h*VHD;
    float* C = g_weighted + (size_t)((b*3 + seg)*HEADS + h)*NQTOT*VHD;
    gemm3_body<0,false>(A, NKTOT, Bv, VPD, nullptr, C, VHD, segN[seg], blockIdx.y<<6, blockIdx.x<<7);
}

// ---------------- Q @ K^T (d=32), 64x64 tile, packed FFMA2 ----------------
__global__ __launch_bounds__(128) void k_qk2()
{
    __shared__ float Qs[32][68];   // k-major
    __shared__ float Ks[32][68];   // k-major (i.e. K^T ready)
    int z = blockIdx.z; int b = z>>3, h = z&7;
    const float* Qb = g_qemb + (size_t)b*NQTOT*ADIM + h*DH;
    const float* Kb = g_kemb + (size_t)b*NKTOT*ADIM + h*DH;
    float* Sb = g_scores + (size_t)z*NQTOT*NKTOT;
    int tid = threadIdx.x;
    int bm = blockIdx.y<<6, bn = blockIdx.x<<6;
    int ra = tid>>1, ca = (tid&1)<<4;
    #pragma unroll
    for (int j=0;j<4;j++){
        float4 q = *(const float4*)(Qb + (size_t)(bm+ra)*ADIM + ca + j*4);
        Qs[ca+j*4+0][ra]=q.x; Qs[ca+j*4+1][ra]=q.y; Qs[ca+j*4+2][ra]=q.z; Qs[ca+j*4+3][ra]=q.w;
        float4 kv = *(const float4*)(Kb + (size_t)(bn+ra)*ADIM + ca + j*4);
        Ks[ca+j*4+0][ra]=kv.x; Ks[ca+j*4+1][ra]=kv.y; Ks[ca+j*4+2][ra]=kv.z; Ks[ca+j*4+3][ra]=kv.w;
    }
    __syncthreads();
    int tx = tid&15, ty = tid>>4;
    unsigned long long acc[8][2];
    #pragma unroll
    for (int i=0;i<8;i++){ acc[i][0]=0ull; acc[i][1]=0ull; }
    #pragma unroll
    for (int kk=0; kk<32; kk++){
        float4 af0 = *(const float4*)&Qs[kk][ty<<3];
        float4 af1 = *(const float4*)&Qs[kk][(ty<<3)+4];
        unsigned long long a2[8];
        a2[0]=pk2(af0.x,af0.x); a2[1]=pk2(af0.y,af0.y);
        a2[2]=pk2(af0.z,af0.z); a2[3]=pk2(af0.w,af0.w);
        a2[4]=pk2(af1.x,af1.x); a2[5]=pk2(af1.y,af1.y);
        a2[6]=pk2(af1.z,af1.z); a2[7]=pk2(af1.w,af1.w);
        ulonglong2 bb = *(const ulonglong2*)&Ks[kk][tx<<2];
        #pragma unroll
        for (int i=0;i<8;i++){
            FFMA2(acc[i][0], a2[i], bb.x);
            FFMA2(acc[i][1], a2[i], bb.y);
        }
    }
    const float scale = 0.17677669529663689f; // 1/sqrt(32)
    #pragma unroll
    for (int i=0;i<8;i++){
        float v0,v1,v2,v3;
        upk2(acc[i][0], v0, v1);
        upk2(acc[i][1], v2, v3);
        float* cp = Sb + (size_t)(bm+(ty<<3)+i)*NKTOT + bn + (tx<<2);
        *(float4*)cp = make_float4(v0*scale, v1*scale, v2*scale, v3*scale);
    }
}

// ---------------- row softmax over 2240 keys (float4) ----------------
__global__ void k_softmax()
{
    __shared__ float4 buf[NKTOT/4];
    __shared__ float red[256];
    float4* p = (float4*)(g_scores + (size_t)blockIdx.x*NKTOT);
    int tid = threadIdx.x;
    float m = -1e30f;
    for (int i=tid;i<NKTOT/4;i+=256){
        float4 x = p[i]; buf[i]=x;
        m = fmaxf(m, fmaxf(fmaxf(x.x,x.y), fmaxf(x.z,x.w)));
    }
    red[tid]=m; __syncthreads();
    for (int o=128;o>0;o>>=1){ if(tid<o) red[tid]=fmaxf(red[tid],red[tid+o]); __syncthreads(); }
    m = red[0]; __syncthreads();
    float s = 0.f;
    for (int i=tid;i<NKTOT/4;i+=256){
        float4 x = buf[i];
        x.x=__expf(x.x-m); x.y=__expf(x.y-m); x.z=__expf(x.z-m); x.w=__expf(x.w-m);
        buf[i]=x; s += x.x+x.y+x.z+x.w;
    }
    red[tid]=s; __syncthreads();
    for (int o=128;o>0;o>>=1){ if(tid<o) red[tid]+=red[tid+o]; __syncthreads(); }
    float inv = 1.0f/red[0];
    for (int i=tid;i<NKTOT/4;i+=256){
        float4 x = buf[i];
        x.x*=inv; x.y*=inv; x.z*=inv; x.w*=inv;
        p[i]=x;
    }
}

// ---------------- gather weighted -> NCHW 96-channel image ----------------
__global__ void k_assemble(const float* __restrict__ W, float* __restrict__ X,
                           int qh, int qw, int qoff, int total)
{
    int idx = blockIdx.x*blockDim.x + threadIdx.x;
    if (idx >= total) return;
    int x = idx % qw;
    int t = idx / qw;
    int y = t % qh; t /= qh;
    int ch = t % 96; int b = t / 96;
    int hd = ch/12; int r2 = ch%12; int seg = r2>>2; int c = r2&3;
    int py=y>>3, ph=y&7, px=x>>3, pw=x&7;
    int n = qoff + py*(qw>>3) + px;
    int d = ((ph<<3)+pw)*4 + c;
    X[idx] = W[ ((size_t)((b*3+seg)*HEADS + hd)*NQTOT + n)*VHD + d ];
}

// ---------------- mbconv expand: grouped 1x1 (96->384, groups 8) + gelu ----------------
__global__ void k_expand(const float* __restrict__ X, const float* __restrict__ w,
                         const float* __restrict__ bias, float* __restrict__ H, int npix)
{
    __shared__ float ws[384*12];
    __shared__ float bs[384];
    int tid = threadIdx.x;
    for (int i=tid;i<4608;i+=256) ws[i]=w[i];
    for (int i=tid;i<384;i+=256) bs[i]=bias[i];
    __syncthreads();
    int pix = blockIdx.x*32 + (tid&31);
    int g = tid>>5;
    int b = blockIdx.y;
    const float* xin = X + ((size_t)b*96 + g*12)*npix + pix;
    float iv[12];
    #pragma unroll
    for (int i=0;i<12;i++) iv[i]=xin[(size_t)i*npix];
    float* hout = H + ((size_t)b*384 + g*48)*npix + pix;
    #pragma unroll 4
    for (int o=0;o<48;o++){
        const float* wr = &ws[(g*48+o)*12];
        float s2 = 0.f;
        #pragma unroll
        for (int i=0;i<12;i++) s2 += iv[i]*wr[i];
        hout[(size_t)o*npix] = gelu_f(s2 + bs[g*48+o]);
    }
}

// ---------------- depthwise 7x7 SAME + gelu ----------------
__global__ void k_dw(const float* __restrict__ H, const float* __restrict__ w,
                     const float* __restrict__ bias, float* __restrict__ O, int Hh, int Ww)
{
    __shared__ float sm[14][39];
    __shared__ float ws[49];
    int bz = blockIdx.z; int ch = bz % 384; int b = bz / 384;
    const float* in = H + ((size_t)(b*384)+ch)*Hh*Ww;
    int tx = threadIdx.x, ty = threadIdx.y; int tid = ty*32+tx;
    if (tid < 49) ws[tid] = w[ch*49 + tid];
    int bx = blockIdx.x*32, by = blockIdx.y*8;
    for (int i=tid;i<14*38;i+=256){
        int ly=i/38, lx=i%38;
        int gy=by+ly-3, gx=bx+lx-3;
        sm[ly][lx] = (gy>=0 && gy<Hh && gx>=0 && gx<Ww) ? in[(size_t)gy*Ww+gx] : 0.f;
    }
    __syncthreads();
    float s2 = 0.f;
    #pragma unroll
    for (int ky=0;ky<7;ky++)
        #pragma unroll
        for (int kx=0;kx<7;kx++)
            s2 += sm[ty+ky][tx+kx]*ws[ky*7+kx];
    O[((size_t)(b*384)+ch)*Hh*Ww + (size_t)(by+ty)*Ww + bx+tx] = gelu_f(s2 + bias[ch]);
}

// ---------------- mbconv proj: grouped 1x1 (384->32, groups 8) ----------------
__global__ void k_proj(const float* __restrict__ H, const float* __restrict__ w,
                       const float* __restrict__ bias, float* __restrict__ O, int npix)
{
    __shared__ float ws[32*48];
    int tid = threadIdx.x;
    for (int i=tid;i<1536;i+=256) ws[i]=w[i];
    __syncthreads();
    int pix = blockIdx.x*32 + (tid&31);
    int g = tid>>5;
    int b = blockIdx.y;
    const float* hin = H + ((size_t)b*384 + g*48)*npix + pix;
    float iv[48];
    #pragma unroll
    for (int i=0;i<48;i++) iv[i]=hin[(size_t)i*npix];
    #pragma unroll
    for (int o=0;o<4;o++){
        int oc = g*4 + o;
        const float* wr = &ws[oc*48];
        float s2 = 0.f;
        #pragma unroll
        for (int i=0;i<48;i++) s2 += iv[i]*wr[i];
        O[((size_t)b*32 + oc)*npix + pix] = s2 + bias[oc];
    }
}

// ---------------- host launch ----------------
#define GETSYM(p, sym) do { cudaGetSymbolAddress((void**)&(p), sym); } while(0)

extern "C" void kernel_launch(void* const* d_in, const int* in_sizes, int n_in,
                              void* d_out, int out_size)
{
    bool dictOrder = (in_sizes[1] == 4194304);
    const float* K0 = (const float*)d_in[0];
    const float* V0 = (const float*)d_in[dictOrder ? 1 : 3];
    const float* K1 = (const float*)d_in[dictOrder ? 2 : 1];
    const float* V1 = (const float*)d_in[dictOrder ? 3 : 4];
    const float* K2 = (const float*)d_in[dictOrder ? 4 : 2];
    const float* V2 = (const float*)d_in[5];
    const float* Q0 = (const float*)d_in[6];
    const float* Q1 = (const float*)d_in[7];
    const float* LNG  = (const float*)d_in[8];
    const float* LNB  = (const float*)d_in[9];
    const float* KW1  = (const float*)d_in[10];
    const float* KB1  = (const float*)d_in[11];
    const float* KW2  = (const float*)d_in[12];
    const float* KB2  = (const float*)d_in[13];
    const float* QW1  = (const float*)d_in[14];
    const float* QB1  = (const float*)d_in[15];
    const float* QW2  = (const float*)d_in[16];
    const float* QB2  = (const float*)d_in[17];
    const float* WEXP = (const float*)d_in[18];
    const float* BEXP = (const float*)d_in[19];
    const float* WDW  = (const float*)d_in[20];
    const float* BDW  = (const float*)d_in[21];
    const float* WPRJ = (const float*)d_in[22];
    const float* BPRJ = (const float*)d_in[23];
    float* out = (float*)d_out;

    float *kseq, *vseq, *qseq, *khid, *kemb, *qhid, *qemb, *x0, *x1, *hid1, *hid2, *wtd;
    GETSYM(kseq, g_kseq); GETSYM(vseq, g_vseq); GETSYM(qseq, g_qseq);
    GETSYM(khid, g_khid); GETSYM(kemb, g_kemb);
    GETSYM(qhid, g_qhid); GETSYM(qemb, g_qemb);
    GETSYM(x0, g_x0); GETSYM(x1, g_x1);
    GETSYM(hid1, g_hid1); GETSYM(hid2, g_hid2);
    GETSYM(wtd, g_weighted);

    // 1) patchify (single merged launch; 17039360 elements total)
    k_patchify_all<<<17039360/256,256>>>(K0,K1,K2,V0,V1,V2,Q0,Q1, kseq, vseq, qseq);

    // 2) layernorm values
    k_layernorm<<<BB*NKTOT,256>>>(vseq, LNG, LNB, VPD);

    // 3) embeddings (gelu MLP), double-buffered FFMA2 GEMMs (Q first so launch #6 is a K-gemm)
    k_gemm3<1,true><<<dim3(ADIM/128, BB*NQTOT/64),128>>>(qseq, QPD, QW1, ADIM, QB1, qhid, ADIM, QPD);
    k_gemm3<0,true><<<dim3(ADIM/128, BB*NQTOT/64),128>>>(qhid, ADIM, QW2, ADIM, QB2, qemb, ADIM, ADIM);
    k_gemm3<1,true><<<dim3(ADIM/128, BB*NKTOT/64),128>>>(kseq, KPD, KW1, ADIM, KB1, khid, ADIM, KPD);
    k_gemm3<0,true><<<dim3(ADIM/128, BB*NKTOT/64),128>>>(khid, ADIM, KW2, ADIM, KB2, kemb, ADIM, ADIM);

    // 4) attention
    k_qk2<<<dim3(NKTOT/64, NQTOT/64, BB*HEADS),128>>>();
    k_softmax<<<BB*HEADS*NQTOT,256>>>();
    k_av3<<<dim3(VHD/128, NQTOT/64, BB*3*HEADS),128>>>();

    // 5) assemble conv inputs
    k_assemble<<<12582912/256,256>>>(wtd, x0, 256,256,    0, 12582912);
    k_assemble<<< 7077888/256,256>>>(wtd, x1, 192,192, 1024,  7077888);

    // 6) mbconv image 0 (256x256)
    {
        int npix = 256*256;
        k_expand<<<dim3(npix/32, BB),256>>>(x0, WEXP, BEXP, hid1, npix);
        k_dw<<<dim3(256/32, 256/8, BB*384), dim3(32,8)>>>(hid1, WDW, BDW, hid2, 256, 256);
        k_proj<<<dim3(npix/32, BB),256>>>(hid2, WPRJ, BPRJ, out, npix);
    }
    // 7) mbconv image 1 (192x192)
    {
        int npix = 192*192;
        k_expand<<<dim3(npix/32, BB),256>>>(x1, WEXP, BEXP, hid1, npix);
        k_dw<<<dim3(192/32, 192/8, BB*384), dim3(32,8)>>>(hid1, WDW, BDW, hid2, 192, 192);
        k_proj<<<dim3(npix/32, BB),256>>>(hid2, WPRJ, BPRJ, out + (size_t)BB*32*256*256, npix);
    }
}

// round 5
// speedup vs baseline: 1.4366x; 1.2333x over previous
#include <cuda_runtime.h>
#include <cuda_bf16.h>
#include <math.h>

// ---------------- problem constants ----------------
#define BB 2
#define HEADS 8
#define DH 32
#define ADIM 256
#define NKTOT 2240          // 1024 + 960 + 256
#define NQTOT 1600          // 1024 + 576
#define KPD 1024            // 8*8*16
#define VPD 2048            // 8*8*32
#define QPD 1024
#define VHD 256             // VPD / HEADS

// ---------------- scratch buffers (static device allocs) ----------------
__device__ float g_kseq[BB*NKTOT*KPD];
__device__ float g_vseq[BB*NKTOT*VPD];
__device__ float g_qseq[BB*NQTOT*QPD];
__device__ float g_khid[BB*NKTOT*ADIM];
__device__ float g_kemb[BB*NKTOT*ADIM];
__device__ float g_qhid[BB*NQTOT*ADIM];
__device__ float g_qemb[BB*NQTOT*ADIM];
__device__ float g_scores[(size_t)BB*HEADS*NQTOT*NKTOT];
__device__ float g_weighted[(size_t)BB*3*HEADS*NQTOT*VHD];
__device__ float g_x0[BB*96*256*256];
__device__ float g_x1[BB*96*192*192];
__device__ float g_hid1[(size_t)BB*384*256*256];
__device__ float g_hid2[(size_t)BB*384*256*256];

__device__ __forceinline__ float gelu_f(float x){
    return 0.5f*x*(1.0f + tanhf(0.7978845608028654f*(x + 0.044715f*x*x*x)));
}

// ---------------- tf32 / mma helpers ----------------
__device__ __forceinline__ float to_tf32(float x){
    float r; asm("cvt.rna.tf32.f32 %0, %1;" : "=f"(r) : "f"(x)); return r;
}
__device__ __forceinline__ float4 cvt4(float4 v){
    v.x=to_tf32(v.x); v.y=to_tf32(v.y); v.z=to_tf32(v.z); v.w=to_tf32(v.w); return v;
}
__device__ __forceinline__ void ldsm4(unsigned& r0,unsigned& r1,unsigned& r2,unsigned& r3, const float* p){
    unsigned addr = (unsigned)__cvta_generic_to_shared(p);
    asm volatile("ldmatrix.sync.aligned.m8n8.x4.shared.b16 {%0,%1,%2,%3}, [%4];"
      : "=r"(r0),"=r"(r1),"=r"(r2),"=r"(r3) : "r"(addr));
}
__device__ __forceinline__ void ldsm2(unsigned& r0,unsigned& r1, const float* p){
    unsigned addr = (unsigned)__cvta_generic_to_shared(p);
    asm volatile("ldmatrix.sync.aligned.m8n8.x2.shared.b16 {%0,%1}, [%2];"
      : "=r"(r0),"=r"(r1) : "r"(addr));
}
__device__ __forceinline__ void mma8(float* d, const unsigned* a, unsigned b0, unsigned b1){
    asm volatile("mma.sync.aligned.m16n8k8.row.col.f32.tf32.tf32.f32 "
      "{%0,%1,%2,%3}, {%4,%5,%6,%7}, {%8,%9}, {%0,%1,%2,%3};"
      : "+f"(d[0]),"+f"(d[1]),"+f"(d[2]),"+f"(d[3])
      : "r"(a[0]),"r"(a[1]),"r"(a[2]),"r"(a[3]), "r"(b0),"r"(b1));
}

// ---------------- merged patchify: all 8 images in one launch ----------------
__global__ void k_patchify_all(
    const float* __restrict__ K0, const float* __restrict__ K1, const float* __restrict__ K2,
    const float* __restrict__ V0, const float* __restrict__ V1, const float* __restrict__ V2,
    const float* __restrict__ Q0, const float* __restrict__ Q1,
    float* __restrict__ kseq, float* __restrict__ vseq, float* __restrict__ qseq)
{
    long gidx = (long)blockIdx.x*blockDim.x + threadIdx.x;  // < 17039360 exactly
    const float* src; float* dst;
    int C, Hh, Ww, nOff, Ntot, fd; long base;
    if      (gidx <  2097152){ src=K0; dst=kseq; C=16; Hh=256; Ww=256; nOff=0;    Ntot=NKTOT; fd=KPD; base=0; }
    else if (gidx <  4063232){ src=K1; dst=kseq; C=16; Hh=192; Ww=320; nOff=1024; Ntot=NKTOT; fd=KPD; base=2097152; }
    else if (gidx <  4587520){ src=K2; dst=kseq; C=16; Hh=128; Ww=128; nOff=1984; Ntot=NKTOT; fd=KPD; base=4063232; }
    else if (gidx <  8781824){ src=V0; dst=vseq; C=32; Hh=256; Ww=256; nOff=0;    Ntot=NKTOT; fd=VPD; base=4587520; }
    else if (gidx < 12713984){ src=V1; dst=vseq; C=32; Hh=192; Ww=320; nOff=1024; Ntot=NKTOT; fd=VPD; base=8781824; }
    else if (gidx < 13762560){ src=V2; dst=vseq; C=32; Hh=128; Ww=128; nOff=1984; Ntot=NKTOT; fd=VPD; base=12713984; }
    else if (gidx < 15859712){ src=Q0; dst=qseq; C=16; Hh=256; Ww=256; nOff=0;    Ntot=NQTOT; fd=QPD; base=13762560; }
    else                     { src=Q1; dst=qseq; C=16; Hh=192; Ww=192; nOff=1024; Ntot=NQTOT; fd=QPD; base=15859712; }
    long idx = gidx - base;
    int x = (int)(idx % Ww);
    long t = idx / Ww;
    int y = (int)(t % Hh); t /= Hh;
    int c = (int)(t % C);  int b = (int)(t / C);
    int hp = y>>3, ph = y&7, wp = x>>3, pw = x&7;
    int n = hp*(Ww>>3) + wp;
    int f = ((ph<<3)+pw)*C + c;
    dst[(size_t)(b*Ntot + nOff + n)*fd + f] = src[idx];
}

// ---------------- layernorm rows (in place) ----------------
__global__ void k_layernorm(float* __restrict__ v, const float* __restrict__ g,
                            const float* __restrict__ bta, int dim)
{
    float* p = v + (size_t)blockIdx.x*dim;
    __shared__ float red[256];
    int tid = threadIdx.x;
    float s=0.f, s2=0.f;
    for (int i=tid;i<dim;i+=256){ float x=p[i]; s+=x; s2+=x*x; }
    red[tid]=s; __syncthreads();
    for (int o=128;o>0;o>>=1){ if(tid<o) red[tid]+=red[tid+o]; __syncthreads(); }
    float mean = red[0]/dim; __syncthreads();
    red[tid]=s2; __syncthreads();
    for (int o=128;o>0;o>>=1){ if(tid<o) red[tid]+=red[tid+o]; __syncthreads(); }
    float var = red[0]/dim - mean*mean;
    float rstd = rsqrtf(var + 1e-5f);
    for (int i=tid;i<dim;i+=256){ float x=p[i]; p[i]=(x-mean)*rstd*g[i]+bta[i]; }
}

// =====================================================================
// TF32 MMA GEMM, config1: BM=64, BN=128, BK=32, 256 threads (8 warps 2x4).
// A row-major [M][lda]; B k-major [K][ldb] (cols bn..bn+127).
// C = act(A@B + bias). Requires M%64==0, N%128==0, K%32==0.
// smem: As 2x64x36 floats + Bs 2x32x132 floats = 52224 B (dynamic).
// =====================================================================
#define AS_STRIDE 36
#define AS_TILE   (64*AS_STRIDE)
#define BS_STRIDE 132
#define BS_TILE   (32*BS_STRIDE)
#define MMA_SMEM  ((2*AS_TILE + 2*BS_TILE)*4)

template<int ACT, bool HASBIAS>
__device__ __forceinline__ void mma_gemm_body(
    const float* __restrict__ A, int lda,
    const float* __restrict__ B, int ldb,
    const float* __restrict__ bias,
    float* __restrict__ C, int ldc,
    int K, int bm, int bn)
{
    extern __shared__ float smf[];
    float* As = smf;
    float* Bs = smf + 2*AS_TILE;
    int tid = threadIdx.x;
    int lane = tid & 31, w = tid >> 5;
    int wm = w >> 2, wn = w & 3;          // 2 x 4 warps, warp tile 32x32

    int arow = tid >> 2, acg = (tid & 3) << 3;   // A loader: 64 rows x 32 k
    int bkr  = tid >> 3, bng = (tid & 7) << 4;   // B loader: 32 k x 128 n

    const float* Ap = A + (size_t)(bm + arow)*lda + acg;
    const float* Bp = B + bn + bng;

    // ldmatrix A per-thread base (float index into a 64x36 tile)
    int mi = lane >> 3, r8 = lane & 7;
    int abase = (wm*32 + (mi&1)*8 + r8)*AS_STRIDE + (mi>>1)*4;
    // B scalar-fragment base: Bs[k][n] k-major
    int bbase = (lane&3)*BS_STRIDE + wn*32 + (lane>>2);

    float acc[2][4][4];
    #pragma unroll
    for (int i=0;i<2;i++)
        #pragma unroll
        for (int j=0;j<4;j++)
            #pragma unroll
            for (int c=0;c<4;c++) acc[i][j][c]=0.f;

    // prologue: tile 0 -> buf 0
    {
        *(float4*)&As[arow*AS_STRIDE + acg    ] = cvt4(*(const float4*)(Ap));
        *(float4*)&As[arow*AS_STRIDE + acg + 4] = cvt4(*(const float4*)(Ap + 4));
        const float* bsrc = Bp + (size_t)bkr*ldb;
        #pragma unroll
        for (int j=0;j<4;j++)
            *(float4*)&Bs[bkr*BS_STRIDE + bng + 4*j] = cvt4(*(const float4*)(bsrc + 4*j));
    }
    __syncthreads();

    int buf = 0;
    for (int k0 = 0; k0 < K; k0 += 32){
        bool nxt = (k0 + 32 < K);
        float4 na0, na1, nb0, nb1, nb2, nb3;
        if (nxt){
            na0 = *(const float4*)(Ap + k0 + 32);
            na1 = *(const float4*)(Ap + k0 + 36);
            const float* bsrc = Bp + (size_t)(k0 + 32 + bkr)*ldb;
            nb0 = *(const float4*)(bsrc);
            nb1 = *(const float4*)(bsrc + 4);
            nb2 = *(const float4*)(bsrc + 8);
            nb3 = *(const float4*)(bsrc + 12);
        }
        const float* Ab = As + buf*AS_TILE;
        const float* Bb = Bs + buf*BS_TILE;
        #pragma unroll
        for (int ks=0; ks<4; ks++){
            unsigned a0[4], a1[4];
            ldsm4(a0[0],a0[1],a0[2],a0[3], Ab + abase + ks*8);
            ldsm4(a1[0],a1[1],a1[2],a1[3], Ab + abase + 16*AS_STRIDE + ks*8);
            #pragma unroll
            for (int nf=0; nf<4; nf++){
                const float* bp0 = Bb + bbase + ks*8*BS_STRIDE + nf*8;
                unsigned b0 = __float_as_uint(bp0[0]);
                unsigned b1 = __float_as_uint(bp0[4*BS_STRIDE]);
                mma8(acc[0][nf], a0, b0, b1);
                mma8(acc[1][nf], a1, b0, b1);
            }
        }
        if (nxt){
            int nb = buf ^ 1;
            float* Aw = As + nb*AS_TILE;
            float* Bw = Bs + nb*BS_TILE;
            *(float4*)&Aw[arow*AS_STRIDE + acg    ] = cvt4(na0);
            *(float4*)&Aw[arow*AS_STRIDE + acg + 4] = cvt4(na1);
            *(float4*)&Bw[bkr*BS_STRIDE + bng     ] = cvt4(nb0);
            *(float4*)&Bw[bkr*BS_STRIDE + bng +  4] = cvt4(nb1);
            *(float4*)&Bw[bkr*BS_STRIDE + bng +  8] = cvt4(nb2);
            *(float4*)&Bw[bkr*BS_STRIDE + bng + 12] = cvt4(nb3);
            __syncthreads();
            buf = nb;
        }
    }

    // epilogue
    int erow = bm + wm*32 + (lane>>2);
    int ecol = bn + wn*32 + (lane&3)*2;
    #pragma unroll
    for (int mf=0; mf<2; mf++){
        int row = erow + mf*16;
        #pragma unroll
        for (int nf=0; nf<4; nf++){
            int col = ecol + nf*8;
            float v0 = acc[mf][nf][0], v1 = acc[mf][nf][1];
            float v2 = acc[mf][nf][2], v3 = acc[mf][nf][3];
            if (HASBIAS){
                float b0v = bias[col], b1v = bias[col+1];
                v0 += b0v; v1 += b1v; v2 += b0v; v3 += b1v;
            }
            if (ACT){ v0=gelu_f(v0); v1=gelu_f(v1); v2=gelu_f(v2); v3=gelu_f(v3); }
            *(float2*)&C[(size_t)row*ldc + col]     = make_float2(v0, v1);
            *(float2*)&C[(size_t)(row+8)*ldc + col] = make_float2(v2, v3);
        }
    }
}

template<int ACT, bool HASBIAS>
__global__ __launch_bounds__(256,2) void k_mma_gemm(
    const float* __restrict__ A, int lda,
    const float* __restrict__ B, int ldb,
    const float* __restrict__ bias,
    float* __restrict__ C, int ldc, int K)
{
    mma_gemm_body<ACT,HASBIAS>(A, lda, B, ldb, bias, C, ldc, K, blockIdx.y*64, blockIdx.x*128);
}

// ---------------- A*V per (b, seg, head), tf32 mma ----------------
__global__ __launch_bounds__(256,2) void k_av_mma()
{
    int z = blockIdx.z;
    int h = z & 7; int t = z >> 3; int seg = t % 3; int b = t / 3;
    const int segOff[3] = {0, 1024, 1984};
    const int segN[3]   = {1024, 960, 256};
    const float* A = g_scores + (size_t)(b*HEADS + h)*NQTOT*NKTOT + segOff[seg];
    const float* Bv = g_vseq + ((size_t)b*NKTOT + segOff[seg])*VPD + h*VHD;
    float* C = g_weighted + (size_t)((b*3 + seg)*HEADS + h)*NQTOT*VHD;
    mma_gemm_body<0,false>(A, NKTOT, Bv, VPD, nullptr, C, VHD, segN[seg], blockIdx.y*64, blockIdx.x*128);
}

// ---------------- Q @ K^T (d=32), tf32 mma, 64x64 tile ----------------
__global__ __launch_bounds__(256,2) void k_qk_mma()
{
    __shared__ float Qs[64*AS_STRIDE];
    __shared__ float Ks2[64*AS_STRIDE];
    int z = blockIdx.z; int b = z>>3, h = z&7;
    const float* Aq = g_qemb + (size_t)b*NQTOT*ADIM + h*DH;
    const float* Bk = g_kemb + (size_t)b*NKTOT*ADIM + h*DH;
    float* Sb = g_scores + (size_t)z*NQTOT*NKTOT;
    int tid = threadIdx.x; int lane = tid&31, w = tid>>5;
    int wm = w >> 1, wn = w & 1;   // 4 x 2 warps, warp tile 16x32
    int bm = blockIdx.y*64, bn = blockIdx.x*64;

    int arow = tid>>2, acg = (tid&3)<<3;
    {
        const float* ap = Aq + (size_t)(bm+arow)*ADIM + acg;
        *(float4*)&Qs[arow*AS_STRIDE + acg    ] = cvt4(*(const float4*)ap);
        *(float4*)&Qs[arow*AS_STRIDE + acg + 4] = cvt4(*(const float4*)(ap+4));
        const float* bp = Bk + (size_t)(bn+arow)*ADIM + acg;
        *(float4*)&Ks2[arow*AS_STRIDE + acg    ] = cvt4(*(const float4*)bp);
        *(float4*)&Ks2[arow*AS_STRIDE + acg + 4] = cvt4(*(const float4*)(bp+4));
    }
    __syncthreads();

    int mi = lane>>3, r8 = lane&7;
    int abase = (wm*16 + (mi&1)*8 + r8)*AS_STRIDE + (mi>>1)*4;
    int bl = lane & 15;
    int bbase = (wn*32 + (bl&7))*AS_STRIDE + ((bl>>3)&1)*4;

    float acc[4][4];
    #pragma unroll
    for (int i=0;i<4;i++)
        #pragma unroll
        for (int c=0;c<4;c++) acc[i][c]=0.f;

    #pragma unroll
    for (int ks=0; ks<4; ks++){
        unsigned a[4];
        ldsm4(a[0],a[1],a[2],a[3], Qs + abase + ks*8);
        #pragma unroll
        for (int nf=0; nf<4; nf++){
            unsigned b0, b1;
            ldsm2(b0, b1, Ks2 + bbase + nf*8*AS_STRIDE + ks*8);
            mma8(acc[nf], a, b0, b1);
        }
    }
    const float scale = 0.17677669529663689f; // 1/sqrt(32)
    int erow = bm + wm*16 + (lane>>2);
    int ecol = bn + wn*32 + (lane&3)*2;
    #pragma unroll
    for (int nf=0; nf<4; nf++){
        int col = ecol + nf*8;
        *(float2*)&Sb[(size_t)erow*NKTOT + col]     = make_float2(acc[nf][0]*scale, acc[nf][1]*scale);
        *(float2*)&Sb[(size_t)(erow+8)*NKTOT + col] = make_float2(acc[nf][2]*scale, acc[nf][3]*scale);
    }
}

// ---------------- row softmax over 2240 keys (float4) ----------------
__global__ void k_softmax()
{
    __shared__ float4 buf[NKTOT/4];
    __shared__ float red[256];
    float4* p = (float4*)(g_scores + (size_t)blockIdx.x*NKTOT);
    int tid = threadIdx.x;
    float m = -1e30f;
    for (int i=tid;i<NKTOT/4;i+=256){
        float4 x = p[i]; buf[i]=x;
        m = fmaxf(m, fmaxf(fmaxf(x.x,x.y), fmaxf(x.z,x.w)));
    }
    red[tid]=m; __syncthreads();
    for (int o=128;o>0;o>>=1){ if(tid<o) red[tid]=fmaxf(red[tid],red[tid+o]); __syncthreads(); }
    m = red[0]; __syncthreads();
    float s = 0.f;
    for (int i=tid;i<NKTOT/4;i+=256){
        float4 x = buf[i];
        x.x=__expf(x.x-m); x.y=__expf(x.y-m); x.z=__expf(x.z-m); x.w=__expf(x.w-m);
        buf[i]=x; s += x.x+x.y+x.z+x.w;
    }
    red[tid]=s; __syncthreads();
    for (int o=128;o>0;o>>=1){ if(tid<o) red[tid]+=red[tid+o]; __syncthreads(); }
    float inv = 1.0f/red[0];
    for (int i=tid;i<NKTOT/4;i+=256){
        float4 x = buf[i];
        x.x*=inv; x.y*=inv; x.z*=inv; x.w*=inv;
        p[i]=x;
    }
}

// ---------------- gather weighted -> NCHW 96-channel image ----------------
__global__ void k_assemble(const float* __restrict__ W, float* __restrict__ X,
                           int qh, int qw, int qoff, int total)
{
    int idx = blockIdx.x*blockDim.x + threadIdx.x;
    if (idx >= total) return;
    int x = idx % qw;
    int t = idx / qw;
    int y = t % qh; t /= qh;
    int ch = t % 96; int b = t / 96;
    int hd = ch/12; int r2 = ch%12; int seg = r2>>2; int c = r2&3;
    int py=y>>3, ph=y&7, px=x>>3, pw=x&7;
    int n = qoff + py*(qw>>3) + px;
    int d = ((ph<<3)+pw)*4 + c;
    X[idx] = W[ ((size_t)((b*3+seg)*HEADS + hd)*NQTOT + n)*VHD + d ];
}

// ---------------- mbconv expand: grouped 1x1 (96->384, groups 8) + gelu ----------------
__global__ void k_expand(const float* __restrict__ X, const float* __restrict__ w,
                         const float* __restrict__ bias, float* __restrict__ H, int npix)
{
    __shared__ float ws[384*12];
    __shared__ float bs[384];
    int tid = threadIdx.x;
    for (int i=tid;i<4608;i+=256) ws[i]=w[i];
    for (int i=tid;i<384;i+=256) bs[i]=bias[i];
    __syncthreads();
    int pix = blockIdx.x*32 + (tid&31);
    int g = tid>>5;
    int b = blockIdx.y;
    const float* xin = X + ((size_t)b*96 + g*12)*npix + pix;
    float iv[12];
    #pragma unroll
    for (int i=0;i<12;i++) iv[i]=xin[(size_t)i*npix];
    float* hout = H + ((size_t)b*384 + g*48)*npix + pix;
    #pragma unroll 4
    for (int o=0;o<48;o++){
        const float* wr = &ws[(g*48+o)*12];
        float s2 = 0.f;
        #pragma unroll
        for (int i=0;i<12;i++) s2 += iv[i]*wr[i];
        hout[(size_t)o*npix] = gelu_f(s2 + bs[g*48+o]);
    }
}

// ---------------- depthwise 7x7 SAME + gelu ----------------
__global__ void k_dw(const float* __restrict__ H, const float* __restrict__ w,
                     const float* __restrict__ bias, float* __restrict__ O, int Hh, int Ww)
{
    __shared__ float sm[14][39];
    __shared__ float ws[49];
    int bz = blockIdx.z; int ch = bz % 384; int b = bz / 384;
    const float* in = H + ((size_t)(b*384)+ch)*Hh*Ww;
    int tx = threadIdx.x, ty = threadIdx.y; int tid = ty*32+tx;
    if (tid < 49) ws[tid] = w[ch*49 + tid];
    int bx = blockIdx.x*32, by = blockIdx.y*8;
    for (int i=tid;i<14*38;i+=256){
        int ly=i/38, lx=i%38;
        int gy=by+ly-3, gx=bx+lx-3;
        sm[ly][lx] = (gy>=0 && gy<Hh && gx>=0 && gx<Ww) ? in[(size_t)gy*Ww+gx] : 0.f;
    }
    __syncthreads();
    float s2 = 0.f;
    #pragma unroll
    for (int ky=0;ky<7;ky++)
        #pragma unroll
        for (int kx=0;kx<7;kx++)
            s2 += sm[ty+ky][tx+kx]*ws[ky*7+kx];
    O[((size_t)(b*384)+ch)*Hh*Ww + (size_t)(by+ty)*Ww + bx+tx] = gelu_f(s2 + bias[ch]);
}

// ---------------- mbconv proj: grouped 1x1 (384->32, groups 8) ----------------
__global__ void k_proj(const float* __restrict__ H, const float* __restrict__ w,
                       const float* __restrict__ bias, float* __restrict__ O, int npix)
{
    __shared__ float ws[32*48];
    int tid = threadIdx.x;
    for (int i=tid;i<1536;i+=256) ws[i]=w[i];
    __syncthreads();
    int pix = blockIdx.x*32 + (tid&31);
    int g = tid>>5;
    int b = blockIdx.y;
    const float* hin = H + ((size_t)b*384 + g*48)*npix + pix;
    float iv[48];
    #pragma unroll
    for (int i=0;i<48;i++) iv[i]=hin[(size_t)i*npix];
    #pragma unroll
    for (int o=0;o<4;o++){
        int oc = g*4 + o;
        const float* wr = &ws[oc*48];
        float s2 = 0.f;
        #pragma unroll
        for (int i=0;i<48;i++) s2 += iv[i]*wr[i];
        O[((size_t)b*32 + oc)*npix + pix] = s2 + bias[oc];
    }
}

// ---------------- host launch ----------------
#define GETSYM(p, sym) do { cudaGetSymbolAddress((void**)&(p), sym); } while(0)

extern "C" void kernel_launch(void* const* d_in, const int* in_sizes, int n_in,
                              void* d_out, int out_size)
{
    bool dictOrder = (in_sizes[1] == 4194304);
    const float* K0 = (const float*)d_in[0];
    const float* V0 = (const float*)d_in[dictOrder ? 1 : 3];
    const float* K1 = (const float*)d_in[dictOrder ? 2 : 1];
    const float* V1 = (const float*)d_in[dictOrder ? 3 : 4];
    const float* K2 = (const float*)d_in[dictOrder ? 4 : 2];
    const float* V2 = (const float*)d_in[5];
    const float* Q0 = (const float*)d_in[6];
    const float* Q1 = (const float*)d_in[7];
    const float* LNG  = (const float*)d_in[8];
    const float* LNB  = (const float*)d_in[9];
    const float* KW1  = (const float*)d_in[10];
    const float* KB1  = (const float*)d_in[11];
    const float* KW2  = (const float*)d_in[12];
    const float* KB2  = (const float*)d_in[13];
    const float* QW1  = (const float*)d_in[14];
    const float* QB1  = (const float*)d_in[15];
    const float* QW2  = (const float*)d_in[16];
    const float* QB2  = (const float*)d_in[17];
    const float* WEXP = (const float*)d_in[18];
    const float* BEXP = (const float*)d_in[19];
    const float* WDW  = (const float*)d_in[20];
    const float* BDW  = (const float*)d_in[21];
    const float* WPRJ = (const float*)d_in[22];
    const float* BPRJ = (const float*)d_in[23];
    float* out = (float*)d_out;

    float *kseq, *vseq, *qseq, *khid, *kemb, *qhid, *qemb, *x0, *x1, *hid1, *hid2, *wtd;
    GETSYM(kseq, g_kseq); GETSYM(vseq, g_vseq); GETSYM(qseq, g_qseq);
    GETSYM(khid, g_khid); GETSYM(kemb, g_kemb);
    GETSYM(qhid, g_qhid); GETSYM(qemb, g_qemb);
    GETSYM(x0, g_x0); GETSYM(x1, g_x1);
    GETSYM(hid1, g_hid1); GETSYM(hid2, g_hid2);
    GETSYM(wtd, g_weighted);

    // opt into >48KB dynamic smem for the mma gemms
    cudaFuncSetAttribute((const void*)k_mma_gemm<1,true>,  cudaFuncAttributeMaxDynamicSharedMemorySize, MMA_SMEM);
    cudaFuncSetAttribute((const void*)k_mma_gemm<0,true>,  cudaFuncAttributeMaxDynamicSharedMemorySize, MMA_SMEM);
    cudaFuncSetAttribute((const void*)k_av_mma,            cudaFuncAttributeMaxDynamicSharedMemorySize, MMA_SMEM);

    // 1) patchify (single merged launch)
    k_patchify_all<<<17039360/256,256>>>(K0,K1,K2,V0,V1,V2,Q0,Q1, kseq, vseq, qseq);

    // 2) layernorm values
    k_layernorm<<<BB*NKTOT,256>>>(vseq, LNG, LNB, VPD);

    // 3) embeddings (gelu MLP), tf32 mma GEMMs
    k_mma_gemm<1,true><<<dim3(2, BB*NKTOT/64), 256, MMA_SMEM>>>(kseq, KPD, KW1, ADIM, KB1, khid, ADIM, KPD);
    k_mma_gemm<0,true><<<dim3(2, BB*NKTOT/64), 256, MMA_SMEM>>>(khid, ADIM, KW2, ADIM, KB2, kemb, ADIM, ADIM);
    k_mma_gemm<1,true><<<dim3(2, BB*NQTOT/64), 256, MMA_SMEM>>>(qseq, QPD, QW1, ADIM, QB1, qhid, ADIM, QPD);
    k_mma_gemm<0,true><<<dim3(2, BB*NQTOT/64), 256, MMA_SMEM>>>(qhid, ADIM, QW2, ADIM, QB2, qemb, ADIM, ADIM);

    // 4) attention
    k_qk_mma<<<dim3(NKTOT/64, NQTOT/64, BB*HEADS), 256>>>();
    k_softmax<<<BB*HEADS*NQTOT,256>>>();
    k_av_mma<<<dim3(2, NQTOT/64, BB*3*HEADS), 256, MMA_SMEM>>>();

    // 5) assemble conv inputs
    k_assemble<<<12582912/256,256>>>(wtd, x0, 256,256,    0, 12582912);
    k_assemble<<< 7077888/256,256>>>(wtd, x1, 192,192, 1024,  7077888);

    // 6) mbconv image 0 (256x256)
    {
        int npix = 256*256;
        k_expand<<<dim3(npix/32, BB),256>>>(x0, WEXP, BEXP, hid1, npix);
        k_dw<<<dim3(256/32, 256/8, BB*384), dim3(32,8)>>>(hid1, WDW, BDW, hid2, 256, 256);
        k_proj<<<dim3(npix/32, BB),256>>>(hid2, WPRJ, BPRJ, out, npix);
    }
    // 7) mbconv image 1 (192x192)
    {
        int npix = 192*192;
        k_expand<<<dim3(npix/32, BB),256>>>(x1, WEXP, BEXP, hid1, npix);
        k_dw<<<dim3(192/32, 192/8, BB*384), dim3(32,8)>>>(hid1, WDW, BDW, hid2, 192, 192);
        k_proj<<<dim3(npix/32, BB),256>>>(hid2, WPRJ, BPRJ, out + (size_t)BB*32*256*256, npix);
    }
}

// round 6
// speedup vs baseline: 1.6374x; 1.1398x over previous
#include <cuda_runtime.h>
#include <cuda_bf16.h>
#include <math.h>

// ---------------- problem constants ----------------
#define BB 2
#define HEADS 8
#define DH 32
#define ADIM 256
#define NKTOT 2240          // 1024 + 960 + 256
#define NQTOT 1600          // 1024 + 576
#define KPD 1024            // 8*8*16
#define VPD 2048            // 8*8*32
#define QPD 1024
#define VHD 256             // VPD / HEADS
#define NROWS (BB*HEADS*NQTOT)   // 25600 score rows

// ---------------- scratch buffers (static device allocs) ----------------
__device__ float g_kseq[BB*NKTOT*KPD];
__device__ float g_vseq[BB*NKTOT*VPD];
__device__ float g_qseq[BB*NQTOT*QPD];
__device__ float g_khid[BB*NKTOT*ADIM];
__device__ float g_kemb[BB*NKTOT*ADIM];
__device__ float g_qhid[BB*NQTOT*ADIM];
__device__ float g_qemb[BB*NQTOT*ADIM];
__device__ float g_scores[(size_t)BB*HEADS*NQTOT*NKTOT];
__device__ float g_weighted[(size_t)BB*3*HEADS*NQTOT*VHD];
__device__ float g_rowm[NROWS];
__device__ float g_rowinv[NROWS];
__device__ float g_x0[BB*96*256*256];
__device__ float g_x1[BB*96*192*192];
__device__ float g_hid1[(size_t)BB*384*256*256];
__device__ float g_hid2[(size_t)BB*384*256*256];

__device__ __forceinline__ float gelu_f(float x){
    return 0.5f*x*(1.0f + tanhf(0.7978845608028654f*(x + 0.044715f*x*x*x)));
}

// ---------------- packed f32x2 helpers ----------------
__device__ __forceinline__ unsigned long long pk2(float lo, float hi){
    unsigned long long r; asm("mov.b64 %0, {%1, %2};" : "=l"(r) : "f"(lo), "f"(hi)); return r;
}
__device__ __forceinline__ void upk2(unsigned long long v, float& lo, float& hi){
    asm("mov.b64 {%0, %1}, %2;" : "=f"(lo), "=f"(hi) : "l"(v));
}
#define FFMA2(acc, a, b) asm("fma.rn.f32x2 %0, %1, %2, %3;" : "=l"(acc) : "l"(a), "l"(b), "l"(acc))

// ---------------- tf32 / mma helpers ----------------
__device__ __forceinline__ float to_tf32(float x){
    float r; asm("cvt.rna.tf32.f32 %0, %1;" : "=f"(r) : "f"(x)); return r;
}
__device__ __forceinline__ float4 cvt4(float4 v){
    v.x=to_tf32(v.x); v.y=to_tf32(v.y); v.z=to_tf32(v.z); v.w=to_tf32(v.w); return v;
}
__device__ __forceinline__ float4 exp4(float4 v, float rm, float ri){
    v.x=__expf(v.x-rm)*ri; v.y=__expf(v.y-rm)*ri;
    v.z=__expf(v.z-rm)*ri; v.w=__expf(v.w-rm)*ri; return v;
}
__device__ __forceinline__ void ldsm4(unsigned& r0,unsigned& r1,unsigned& r2,unsigned& r3, const float* p){
    unsigned addr = (unsigned)__cvta_generic_to_shared(p);
    asm volatile("ldmatrix.sync.aligned.m8n8.x4.shared.b16 {%0,%1,%2,%3}, [%4];"
      : "=r"(r0),"=r"(r1),"=r"(r2),"=r"(r3) : "r"(addr));
}
__device__ __forceinline__ void ldsm2(unsigned& r0,unsigned& r1, const float* p){
    unsigned addr = (unsigned)__cvta_generic_to_shared(p);
    asm volatile("ldmatrix.sync.aligned.m8n8.x2.shared.b16 {%0,%1}, [%2];"
      : "=r"(r0),"=r"(r1) : "r"(addr));
}
__device__ __forceinline__ void mma8(float* d, const unsigned* a, unsigned b0, unsigned b1){
    asm volatile("mma.sync.aligned.m16n8k8.row.col.f32.tf32.tf32.f32 "
      "{%0,%1,%2,%3}, {%4,%5,%6,%7}, {%8,%9}, {%0,%1,%2,%3};"
      : "+f"(d[0]),"+f"(d[1]),"+f"(d[2]),"+f"(d[3])
      : "r"(a[0]),"r"(a[1]),"r"(a[2]),"r"(a[3]), "r"(b0),"r"(b1));
}

// ---------------- merged patchify: all 8 images in one launch ----------------
__global__ void k_patchify_all(
    const float* __restrict__ K0, const float* __restrict__ K1, const float* __restrict__ K2,
    const float* __restrict__ V0, const float* __restrict__ V1, const float* __restrict__ V2,
    const float* __restrict__ Q0, const float* __restrict__ Q1,
    float* __restrict__ kseq, float* __restrict__ vseq, float* __restrict__ qseq)
{
    long gidx = (long)blockIdx.x*blockDim.x + threadIdx.x;  // < 17039360 exactly
    const float* src; float* dst;
    int C, Hh, Ww, nOff, Ntot, fd; long base;
    if      (gidx <  2097152){ src=K0; dst=kseq; C=16; Hh=256; Ww=256; nOff=0;    Ntot=NKTOT; fd=KPD; base=0; }
    else if (gidx <  4063232){ src=K1; dst=kseq; C=16; Hh=192; Ww=320; nOff=1024; Ntot=NKTOT; fd=KPD; base=2097152; }
    else if (gidx <  4587520){ src=K2; dst=kseq; C=16; Hh=128; Ww=128; nOff=1984; Ntot=NKTOT; fd=KPD; base=4063232; }
    else if (gidx <  8781824){ src=V0; dst=vseq; C=32; Hh=256; Ww=256; nOff=0;    Ntot=NKTOT; fd=VPD; base=4587520; }
    else if (gidx < 12713984){ src=V1; dst=vseq; C=32; Hh=192; Ww=320; nOff=1024; Ntot=NKTOT; fd=VPD; base=8781824; }
    else if (gidx < 13762560){ src=V2; dst=vseq; C=32; Hh=128; Ww=128; nOff=1984; Ntot=NKTOT; fd=VPD; base=12713984; }
    else if (gidx < 15859712){ src=Q0; dst=qseq; C=16; Hh=256; Ww=256; nOff=0;    Ntot=NQTOT; fd=QPD; base=13762560; }
    else                     { src=Q1; dst=qseq; C=16; Hh=192; Ww=192; nOff=1024; Ntot=NQTOT; fd=QPD; base=15859712; }
    long idx = gidx - base;
    int x = (int)(idx % Ww);
    long t = idx / Ww;
    int y = (int)(t % Hh); t /= Hh;
    int c = (int)(t % C);  int b = (int)(t / C);
    int hp = y>>3, ph = y&7, wp = x>>3, pw = x&7;
    int n = hp*(Ww>>3) + wp;
    int f = ((ph<<3)+pw)*C + c;
    dst[(size_t)(b*Ntot + nOff + n)*fd + f] = src[idx];
}

// ---------------- layernorm rows (in place) ----------------
__global__ void k_layernorm(float* __restrict__ v, const float* __restrict__ g,
                            const float* __restrict__ bta, int dim)
{
    float* p = v + (size_t)blockIdx.x*dim;
    __shared__ float red[256];
    int tid = threadIdx.x;
    float s=0.f, s2=0.f;
    for (int i=tid;i<dim;i+=256){ float x=p[i]; s+=x; s2+=x*x; }
    red[tid]=s; __syncthreads();
    for (int o=128;o>0;o>>=1){ if(tid<o) red[tid]+=red[tid+o]; __syncthreads(); }
    float mean = red[0]/dim; __syncthreads();
    red[tid]=s2; __syncthreads();
    for (int o=128;o>0;o>>=1){ if(tid<o) red[tid]+=red[tid+o]; __syncthreads(); }
    float var = red[0]/dim - mean*mean;
    float rstd = rsqrtf(var + 1e-5f);
    for (int i=tid;i<dim;i+=256){ float x=p[i]; p[i]=(x-mean)*rstd*g[i]+bta[i]; }
}

// =====================================================================
// TF32 MMA GEMM: BM=64, BN=128, BK=32, 256 threads (8 warps 2x4).
// Optional fused softmax-exp on A (DOEXP): a = exp(a - rowm)*rowinv.
// =====================================================================
#define AS_STRIDE 36
#define AS_TILE   (64*AS_STRIDE)
#define BS_STRIDE 132
#define BS_TILE   (32*BS_STRIDE)
#define MMA_SMEM  ((2*AS_TILE + 2*BS_TILE)*4)

template<int ACT, bool HASBIAS, bool DOEXP>
__device__ __forceinline__ void mma_gemm_body(
    const float* __restrict__ A, int lda,
    const float* __restrict__ B, int ldb,
    const float* __restrict__ bias,
    const float* __restrict__ rowm, const float* __restrict__ rowinv,
    float* __restrict__ C, int ldc,
    int K, int bm, int bn)
{
    extern __shared__ float smf[];
    float* As = smf;
    float* Bs = smf + 2*AS_TILE;
    int tid = threadIdx.x;
    int lane = tid & 31, w = tid >> 5;
    int wm = w >> 2, wn = w & 3;          // 2 x 4 warps, warp tile 32x32

    int arow = tid >> 2, acg = (tid & 3) << 3;   // A loader: 64 rows x 32 k
    int bkr  = tid >> 3, bng = (tid & 7) << 4;   // B loader: 32 k x 128 n

    float rm = 0.f, ri = 0.f;
    if (DOEXP){ rm = rowm[bm+arow]; ri = rowinv[bm+arow]; }

    const float* Ap = A + (size_t)(bm + arow)*lda + acg;
    const float* Bp = B + bn + bng;

    int mi = lane >> 3, r8 = lane & 7;
    int abase = (wm*32 + (mi&1)*8 + r8)*AS_STRIDE + (mi>>1)*4;
    int bbase = (lane&3)*BS_STRIDE + wn*32 + (lane>>2);

    float acc[2][4][4];
    #pragma unroll
    for (int i=0;i<2;i++)
        #pragma unroll
        for (int j=0;j<4;j++)
            #pragma unroll
            for (int c=0;c<4;c++) acc[i][j][c]=0.f;

    // prologue: tile 0 -> buf 0
    {
        float4 a0 = *(const float4*)(Ap);
        float4 a1 = *(const float4*)(Ap + 4);
        if (DOEXP){ a0 = exp4(a0, rm, ri); a1 = exp4(a1, rm, ri); }
        *(float4*)&As[arow*AS_STRIDE + acg    ] = cvt4(a0);
        *(float4*)&As[arow*AS_STRIDE + acg + 4] = cvt4(a1);
        const float* bsrc = Bp + (size_t)bkr*ldb;
        #pragma unroll
        for (int j=0;j<4;j++)
            *(float4*)&Bs[bkr*BS_STRIDE + bng + 4*j] = cvt4(*(const float4*)(bsrc + 4*j));
    }
    __syncthreads();

    int buf = 0;
    for (int k0 = 0; k0 < K; k0 += 32){
        bool nxt = (k0 + 32 < K);
        float4 na0, na1, nb0, nb1, nb2, nb3;
        if (nxt){
            na0 = *(const float4*)(Ap + k0 + 32);
            na1 = *(const float4*)(Ap + k0 + 36);
            const float* bsrc = Bp + (size_t)(k0 + 32 + bkr)*ldb;
            nb0 = *(const float4*)(bsrc);
            nb1 = *(const float4*)(bsrc + 4);
            nb2 = *(const float4*)(bsrc + 8);
            nb3 = *(const float4*)(bsrc + 12);
        }
        const float* Ab = As + buf*AS_TILE;
        const float* Bb = Bs + buf*BS_TILE;
        #pragma unroll
        for (int ks=0; ks<4; ks++){
            unsigned a0[4], a1[4];
            ldsm4(a0[0],a0[1],a0[2],a0[3], Ab + abase + ks*8);
            ldsm4(a1[0],a1[1],a1[2],a1[3], Ab + abase + 16*AS_STRIDE + ks*8);
            #pragma unroll
            for (int nf=0; nf<4; nf++){
                const float* bp0 = Bb + bbase + ks*8*BS_STRIDE + nf*8;
                unsigned b0 = __float_as_uint(bp0[0]);
                unsigned b1 = __float_as_uint(bp0[4*BS_STRIDE]);
                mma8(acc[0][nf], a0, b0, b1);
                mma8(acc[1][nf], a1, b0, b1);
            }
        }
        if (nxt){
            int nb = buf ^ 1;
            float* Aw = As + nb*AS_TILE;
            float* Bw = Bs + nb*BS_TILE;
            if (DOEXP){ na0 = exp4(na0, rm, ri); na1 = exp4(na1, rm, ri); }
            *(float4*)&Aw[arow*AS_STRIDE + acg    ] = cvt4(na0);
            *(float4*)&Aw[arow*AS_STRIDE + acg + 4] = cvt4(na1);
            *(float4*)&Bw[bkr*BS_STRIDE + bng     ] = cvt4(nb0);
            *(float4*)&Bw[bkr*BS_STRIDE + bng +  4] = cvt4(nb1);
            *(float4*)&Bw[bkr*BS_STRIDE + bng +  8] = cvt4(nb2);
            *(float4*)&Bw[bkr*BS_STRIDE + bng + 12] = cvt4(nb3);
            __syncthreads();
            buf = nb;
        }
    }

    // epilogue
    int erow = bm + wm*32 + (lane>>2);
    int ecol = bn + wn*32 + (lane&3)*2;
    #pragma unroll
    for (int mf=0; mf<2; mf++){
        int row = erow + mf*16;
        #pragma unroll
        for (int nf=0; nf<4; nf++){
            int col = ecol + nf*8;
            float v0 = acc[mf][nf][0], v1 = acc[mf][nf][1];
            float v2 = acc[mf][nf][2], v3 = acc[mf][nf][3];
            if (HASBIAS){
                float b0v = bias[col], b1v = bias[col+1];
                v0 += b0v; v1 += b1v; v2 += b0v; v3 += b1v;
            }
            if (ACT){ v0=gelu_f(v0); v1=gelu_f(v1); v2=gelu_f(v2); v3=gelu_f(v3); }
            *(float2*)&C[(size_t)row*ldc + col]     = make_float2(v0, v1);
            *(float2*)&C[(size_t)(row+8)*ldc + col] = make_float2(v2, v3);
        }
    }
}

template<int ACT, bool HASBIAS>
__global__ __launch_bounds__(256,2) void k_mma_gemm(
    const float* __restrict__ A, int lda,
    const float* __restrict__ B, int ldb,
    const float* __restrict__ bias,
    float* __restrict__ C, int ldc, int K)
{
    mma_gemm_body<ACT,HASBIAS,false>(A, lda, B, ldb, bias, nullptr, nullptr, C, ldc, K, blockIdx.y*64, blockIdx.x*128);
}

// ---------------- A*V per (b, seg, head), tf32 mma, softmax-exp fused ----------------
__global__ __launch_bounds__(256,2) void k_av_mma()
{
    int z = blockIdx.z;
    int h = z & 7; int t = z >> 3; int seg = t % 3; int b = t / 3;
    const int segOff[3] = {0, 1024, 1984};
    const int segN[3]   = {1024, 960, 256};
    const float* A = g_scores + (size_t)(b*HEADS + h)*NQTOT*NKTOT + segOff[seg];
    const float* Bv = g_vseq + ((size_t)b*NKTOT + segOff[seg])*VPD + h*VHD;
    const float* rm = g_rowm   + (size_t)(b*HEADS + h)*NQTOT;
    const float* ri = g_rowinv + (size_t)(b*HEADS + h)*NQTOT;
    float* C = g_weighted + (size_t)((b*3 + seg)*HEADS + h)*NQTOT*VHD;
    mma_gemm_body<0,false,true>(A, NKTOT, Bv, VPD, nullptr, rm, ri, C, VHD, segN[seg], blockIdx.y*64, blockIdx.x*128);
}

// ---------------- Q @ K^T (d=32), tf32 mma, 64x64 tile ----------------
__global__ __launch_bounds__(256,2) void k_qk_mma()
{
    __shared__ float Qs[64*AS_STRIDE];
    __shared__ float Ks2[64*AS_STRIDE];
    int z = blockIdx.z; int b = z>>3, h = z&7;
    const float* Aq = g_qemb + (size_t)b*NQTOT*ADIM + h*DH;
    const float* Bk = g_kemb + (size_t)b*NKTOT*ADIM + h*DH;
    float* Sb = g_scores + (size_t)z*NQTOT*NKTOT;
    int tid = threadIdx.x; int lane = tid&31, w = tid>>5;
    int wm = w >> 1, wn = w & 1;   // 4 x 2 warps, warp tile 16x32
    int bm = blockIdx.y*64, bn = blockIdx.x*64;

    int arow = tid>>2, acg = (tid&3)<<3;
    {
        const float* ap = Aq + (size_t)(bm+arow)*ADIM + acg;
        *(float4*)&Qs[arow*AS_STRIDE + acg    ] = cvt4(*(const float4*)ap);
        *(float4*)&Qs[arow*AS_STRIDE + acg + 4] = cvt4(*(const float4*)(ap+4));
        const float* bp = Bk + (size_t)(bn+arow)*ADIM + acg;
        *(float4*)&Ks2[arow*AS_STRIDE + acg    ] = cvt4(*(const float4*)bp);
        *(float4*)&Ks2[arow*AS_STRIDE + acg + 4] = cvt4(*(const float4*)(bp+4));
    }
    __syncthreads();

    int mi = lane>>3, r8 = lane&7;
    int abase = (wm*16 + (mi&1)*8 + r8)*AS_STRIDE + (mi>>1)*4;
    int bl = lane & 15;
    int bbase = (wn*32 + (bl&7))*AS_STRIDE + ((bl>>3)&1)*4;

    float acc[4][4];
    #pragma unroll
    for (int i=0;i<4;i++)
        #pragma unroll
        for (int c=0;c<4;c++) acc[i][c]=0.f;

    #pragma unroll
    for (int ks=0; ks<4; ks++){
        unsigned a[4];
        ldsm4(a[0],a[1],a[2],a[3], Qs + abase + ks*8);
        #pragma unroll
        for (int nf=0; nf<4; nf++){
            unsigned b0, b1;
            ldsm2(b0, b1, Ks2 + bbase + nf*8*AS_STRIDE + ks*8);
            mma8(acc[nf], a, b0, b1);
        }
    }
    const float scale = 0.17677669529663689f; // 1/sqrt(32)
    int erow = bm + wm*16 + (lane>>2);
    int ecol = bn + wn*32 + (lane&3)*2;
    #pragma unroll
    for (int nf=0; nf<4; nf++){
        int col = ecol + nf*8;
        *(float2*)&Sb[(size_t)erow*NKTOT + col]     = make_float2(acc[nf][0]*scale, acc[nf][1]*scale);
        *(float2*)&Sb[(size_t)(erow+8)*NKTOT + col] = make_float2(acc[nf][2]*scale, acc[nf][3]*scale);
    }
}

// ---------------- row stats: max + 1/sum(exp) per score row ----------------
__global__ void k_rowstat()
{
    __shared__ float red[256];
    const float4* p = (const float4*)(g_scores + (size_t)blockIdx.x*NKTOT);
    int tid = threadIdx.x;
    float m = -1e30f;
    for (int i=tid;i<NKTOT/4;i+=256){
        float4 x = p[i];
        m = fmaxf(m, fmaxf(fmaxf(x.x,x.y), fmaxf(x.z,x.w)));
    }
    red[tid]=m; __syncthreads();
    for (int o=128;o>0;o>>=1){ if(tid<o) red[tid]=fmaxf(red[tid],red[tid+o]); __syncthreads(); }
    m = red[0]; __syncthreads();
    float s = 0.f;
    for (int i=tid;i<NKTOT/4;i+=256){
        float4 x = p[i];
        s += __expf(x.x-m) + __expf(x.y-m) + __expf(x.z-m) + __expf(x.w-m);
    }
    red[tid]=s; __syncthreads();
    for (int o=128;o>0;o>>=1){ if(tid<o) red[tid]+=red[tid+o]; __syncthreads(); }
    if (tid==0){ g_rowm[blockIdx.x] = m; g_rowinv[blockIdx.x] = 1.0f/red[0]; }
}

// ---------------- coalesced gather: weighted -> NCHW 96-channel image ----------------
// One thread per float4 of W (contiguous reads); 4 scalar scattered writes (32B sectors).
__global__ void k_assemble2(const float* __restrict__ W, float* __restrict__ X,
                            int qh, int qw, int qoff, int nq, long total4)
{
    long idx = (long)blockIdx.x*blockDim.x + threadIdx.x;
    if (idx >= total4) return;
    int d4 = (int)(idx & 63);              // VHD/4 = 64 groups
    long t = idx >> 6;
    int n  = (int)(t % nq); t /= nq;
    int hd = (int)(t & 7);  t >>= 3;
    int seg= (int)(t % 3);  int b = (int)(t/3);
    float4 v = *(const float4*)&W[ (((size_t)((b*3+seg)*HEADS+hd)*NQTOT) + qoff + n)*VHD + (d4<<2) ];
    int ph = d4>>3, pw = d4&7;
    int wpatches = qw>>3;
    int py = n / wpatches, px = n % wpatches;
    int y = py*8+ph, x = px*8+pw;
    size_t hw = (size_t)qh*qw;
    size_t base = ((size_t)b*96 + hd*12 + seg*4)*hw + (size_t)y*qw + x;
    X[base] = v.x; X[base+hw] = v.y; X[base+2*hw] = v.z; X[base+3*hw] = v.w;
}

// ---------------- mbconv expand: grouped 1x1 (96->384, groups 8) + gelu ----------------
__global__ void k_expand(const float* __restrict__ X, const float* __restrict__ w,
                         const float* __restrict__ bias, float* __restrict__ H, int npix)
{
    __shared__ float ws[384*12];
    __shared__ float bs[384];
    int tid = threadIdx.x;
    for (int i=tid;i<4608;i+=256) ws[i]=w[i];
    for (int i=tid;i<384;i+=256) bs[i]=bias[i];
    __syncthreads();
    int pix = blockIdx.x*32 + (tid&31);
    int g = tid>>5;
    int b = blockIdx.y;
    const float* xin = X + ((size_t)b*96 + g*12)*npix + pix;
    float iv[12];
    #pragma unroll
    for (int i=0;i<12;i++) iv[i]=xin[(size_t)i*npix];
    float* hout = H + ((size_t)b*384 + g*48)*npix + pix;
    #pragma unroll 4
    for (int o=0;o<48;o++){
        const float* wr = &ws[(g*48+o)*12];
        float s2 = 0.f;
        #pragma unroll
        for (int i=0;i<12;i++) s2 += iv[i]*wr[i];
        hout[(size_t)o*npix] = gelu_f(s2 + bs[g*48+o]);
    }
}

// ---------------- depthwise 7x7 SAME + gelu, FFMA2, 4 px/thread ----------------
// block (8,8)=64 thr, tile 32x8 outputs. Dual-copy paired smem:
//   PA[r][i] = (v[2i], v[2i+1]),  PB[r][i] = (v[2i+1], v[2i+2])
// halo row v[0..37] maps to gx = bx-3 .. bx+34.
__global__ void k_dw2(const float* __restrict__ H, const float* __restrict__ w,
                      const float* __restrict__ bias, float* __restrict__ O, int Hh, int Ww)
{
    __shared__ float2 PA[14][20];
    __shared__ float2 PB[14][20];
    __shared__ float ws[49];
    int bz = blockIdx.z; int ch = bz % 384; int b = bz / 384;
    const float* in = H + ((size_t)(b*384)+ch)*Hh*Ww;
    int tx = threadIdx.x, ty = threadIdx.y; int tid = ty*8+tx;
    if (tid < 49) ws[tid] = w[ch*49 + tid];
    int bx = blockIdx.x*32, by = blockIdx.y*8;
    for (int i=tid;i<14*38;i+=64){
        int ly=i/38, lx=i%38;
        int gy=by+ly-3, gx=bx+lx-3;
        float val = (gy>=0 && gy<Hh && gx>=0 && gx<Ww) ? in[(size_t)gy*Ww+gx] : 0.f;
        if ((lx&1)==0){
            PA[ly][lx>>1].x = val;
            if (lx>=2) PB[ly][(lx>>1)-1].y = val;
        } else {
            PA[ly][lx>>1].y = val;
            PB[ly][lx>>1].x = val;
        }
    }
    __syncthreads();

    unsigned long long acc0 = 0ull, acc1 = 0ull;  // pixels (4tx,4tx+1), (4tx+2,4tx+3)
    int p2 = tx*2;
    #pragma unroll
    for (int ky=0;ky<7;ky++){
        const float2* ra = PA[ty+ky];
        const float2* rb = PB[ty+ky];
        unsigned long long A0 = *(const unsigned long long*)&ra[p2];
        unsigned long long A1 = *(const unsigned long long*)&ra[p2+1];
        unsigned long long A2 = *(const unsigned long long*)&ra[p2+2];
        unsigned long long A3 = *(const unsigned long long*)&ra[p2+3];
        unsigned long long A4 = *(const unsigned long long*)&ra[p2+4];
        unsigned long long B0 = *(const unsigned long long*)&rb[p2];
        unsigned long long B1 = *(const unsigned long long*)&rb[p2+1];
        unsigned long long B2 = *(const unsigned long long*)&rb[p2+2];
        unsigned long long B3 = *(const unsigned long long*)&rb[p2+3];
        float w0=ws[ky*7+0], w1=ws[ky*7+1], w2=ws[ky*7+2], w3=ws[ky*7+3];
        float w4=ws[ky*7+4], w5=ws[ky*7+5], w6=ws[ky*7+6];
        unsigned long long W0=pk2(w0,w0), W1=pk2(w1,w1), W2=pk2(w2,w2), W3=pk2(w3,w3);
        unsigned long long W4=pk2(w4,w4), W5=pk2(w5,w5), W6=pk2(w6,w6);
        FFMA2(acc0, A0, W0); FFMA2(acc1, A1, W0);
        FFMA2(acc0, B0, W1); FFMA2(acc1, B1, W1);
        FFMA2(acc0, A1, W2); FFMA2(acc1, A2, W2);
        FFMA2(acc0, B1, W3); FFMA2(acc1, B2, W3);
        FFMA2(acc0, A2, W4); FFMA2(acc1, A3, W4);
        FFMA2(acc0, B2, W5); FFMA2(acc1, B3, W5);
        FFMA2(acc0, A3, W6); FFMA2(acc1, A4, W6);
    }
    float bsv = bias[ch];
    float o0,o1,o2,o3;
    upk2(acc0, o0, o1); upk2(acc1, o2, o3);
    float4 outv = make_float4(gelu_f(o0+bsv), gelu_f(o1+bsv), gelu_f(o2+bsv), gelu_f(o3+bsv));
    *(float4*)&O[((size_t)(b*384)+ch)*Hh*Ww + (size_t)(by+ty)*Ww + bx + tx*4] = outv;
}

// ---------------- mbconv proj: grouped 1x1 (384->32, groups 8) ----------------
__global__ void k_proj(const float* __restrict__ H, const float* __restrict__ w,
                       const float* __restrict__ bias, float* __restrict__ O, int npix)
{
    __shared__ float ws[32*48];
    int tid = threadIdx.x;
    for (int i=tid;i<1536;i+=256) ws[i]=w[i];
    __syncthreads();
    int pix = blockIdx.x*32 + (tid&31);
    int g = tid>>5;
    int b = blockIdx.y;
    const float* hin = H + ((size_t)b*384 + g*48)*npix + pix;
    float iv[48];
    #pragma unroll
    for (int i=0;i<48;i++) iv[i]=hin[(size_t)i*npix];
    #pragma unroll
    for (int o=0;o<4;o++){
        int oc = g*4 + o;
        const float* wr = &ws[oc*48];
        float s2 = 0.f;
        #pragma unroll
        for (int i=0;i<48;i++) s2 += iv[i]*wr[i];
        O[((size_t)b*32 + oc)*npix + pix] = s2 + bias[oc];
    }
}

// ---------------- host launch ----------------
#define GETSYM(p, sym) do { cudaGetSymbolAddress((void**)&(p), sym); } while(0)

extern "C" void kernel_launch(void* const* d_in, const int* in_sizes, int n_in,
                              void* d_out, int out_size)
{
    bool dictOrder = (in_sizes[1] == 4194304);
    const float* K0 = (const float*)d_in[0];
    const float* V0 = (const float*)d_in[dictOrder ? 1 : 3];
    const float* K1 = (const float*)d_in[dictOrder ? 2 : 1];
    const float* V1 = (const float*)d_in[dictOrder ? 3 : 4];
    const float* K2 = (const float*)d_in[dictOrder ? 4 : 2];
    const float* V2 = (const float*)d_in[5];
    const float* Q0 = (const float*)d_in[6];
    const float* Q1 = (const float*)d_in[7];
    const float* LNG  = (const float*)d_in[8];
    const float* LNB  = (const float*)d_in[9];
    const float* KW1  = (const float*)d_in[10];
    const float* KB1  = (const float*)d_in[11];
    const float* KW2  = (const float*)d_in[12];
    const float* KB2  = (const float*)d_in[13];
    const float* QW1  = (const float*)d_in[14];
    const float* QB1  = (const float*)d_in[15];
    const float* QW2  = (const float*)d_in[16];
    const float* QB2  = (const float*)d_in[17];
    const float* WEXP = (const float*)d_in[18];
    const float* BEXP = (const float*)d_in[19];
    const float* WDW  = (const float*)d_in[20];
    const float* BDW  = (const float*)d_in[21];
    const float* WPRJ = (const float*)d_in[22];
    const float* BPRJ = (const float*)d_in[23];
    float* out = (float*)d_out;

    float *kseq, *vseq, *qseq, *khid, *kemb, *qhid, *qemb, *x0, *x1, *hid1, *hid2, *wtd;
    GETSYM(kseq, g_kseq); GETSYM(vseq, g_vseq); GETSYM(qseq, g_qseq);
    GETSYM(khid, g_khid); GETSYM(kemb, g_kemb);
    GETSYM(qhid, g_qhid); GETSYM(qemb, g_qemb);
    GETSYM(x0, g_x0); GETSYM(x1, g_x1);
    GETSYM(hid1, g_hid1); GETSYM(hid2, g_hid2);
    GETSYM(wtd, g_weighted);

    cudaFuncSetAttribute((const void*)k_mma_gemm<1,true>,  cudaFuncAttributeMaxDynamicSharedMemorySize, MMA_SMEM);
    cudaFuncSetAttribute((const void*)k_mma_gemm<0,true>,  cudaFuncAttributeMaxDynamicSharedMemorySize, MMA_SMEM);
    cudaFuncSetAttribute((const void*)k_av_mma,            cudaFuncAttributeMaxDynamicSharedMemorySize, MMA_SMEM);

    // 1) patchify (single merged launch)
    k_patchify_all<<<17039360/256,256>>>(K0,K1,K2,V0,V1,V2,Q0,Q1, kseq, vseq, qseq);

    // 2-5) embeddings (gelu MLP), tf32 mma GEMMs
    k_mma_gemm<1,true><<<dim3(2, BB*NKTOT/64), 256, MMA_SMEM>>>(kseq, KPD, KW1, ADIM, KB1, khid, ADIM, KPD);
    k_mma_gemm<0,true><<<dim3(2, BB*NKTOT/64), 256, MMA_SMEM>>>(khid, ADIM, KW2, ADIM, KB2, kemb, ADIM, ADIM);
    k_mma_gemm<1,true><<<dim3(2, BB*NQTOT/64), 256, MMA_SMEM>>>(qseq, QPD, QW1, ADIM, QB1, qhid, ADIM, QPD);
    k_mma_gemm<0,true><<<dim3(2, BB*NQTOT/64), 256, MMA_SMEM>>>(qhid, ADIM, QW2, ADIM, QB2, qemb, ADIM, ADIM);

    // 6) QK  (launch #6 -> captured by ncu -s 5 -c 1)
    k_qk_mma<<<dim3(NKTOT/64, NQTOT/64, BB*HEADS), 256>>>();

    // 7) row stats (replaces full softmax)
    k_rowstat<<<NROWS,256>>>();

    // 8) layernorm values (only needed before AV)
    k_layernorm<<<BB*NKTOT,256>>>(vseq, LNG, LNB, VPD);

    // 9) AV with fused softmax-exp
    k_av_mma<<<dim3(2, NQTOT/64, BB*3*HEADS), 256, MMA_SMEM>>>();

    // 10-11) assemble conv inputs (coalesced)
    k_assemble2<<<3145728/256,256>>>(wtd, x0, 256,256,    0, 1024, 3145728L);
    k_assemble2<<<1769472/256,256>>>(wtd, x1, 192,192, 1024,  576, 1769472L);

    // 12-14) mbconv image 0 (256x256)
    {
        int npix = 256*256;
        k_expand<<<dim3(npix/32, BB),256>>>(x0, WEXP, BEXP, hid1, npix);
        k_dw2<<<dim3(256/32, 256/8, BB*384), dim3(8,8)>>>(hid1, WDW, BDW, hid2, 256, 256);
        k_proj<<<dim3(npix/32, BB),256>>>(hid2, WPRJ, BPRJ, out, npix);
    }
    // 15-17) mbconv image 1 (192x192)
    {
        int npix = 192*192;
        k_expand<<<dim3(npix/32, BB),256>>>(x1, WEXP, BEXP, hid1, npix);
        k_dw2<<<dim3(192/32, 192/8, BB*384), dim3(8,8)>>>(hid1, WDW, BDW, hid2, 192, 192);
        k_proj<<<dim3(npix/32, BB),256>>>(hid2, WPRJ, BPRJ, out + (size_t)BB*32*256*256, npix);
    }
}

// round 7
// speedup vs baseline: 1.8745x; 1.1448x over previous
#include <cuda_runtime.h>
#include <cuda_bf16.h>
#include <math.h>

// ---------------- problem constants ----------------
#define BB 2
#define HEADS 8
#define DH 32
#define ADIM 256
#define NKTOT 2240          // 1024 + 960 + 256
#define NQTOT 1600          // 1024 + 576
#define KPD 1024            // 8*8*16
#define VPD 2048            // 8*8*32
#define QPD 1024
#define VHD 256             // VPD / HEADS
#define NROWS (BB*HEADS*NQTOT)   // 25600 score rows

// ---------------- scratch buffers (static device allocs) ----------------
__device__ float g_kseq[BB*NKTOT*KPD];
__device__ float g_vseq[BB*NKTOT*VPD];
__device__ float g_qseq[BB*NQTOT*QPD];
__device__ float g_khid[BB*NKTOT*ADIM];
__device__ float g_kemb[BB*NKTOT*ADIM];
__device__ float g_qhid[BB*NQTOT*ADIM];
__device__ float g_qemb[BB*NQTOT*ADIM];
__device__ float g_scores[(size_t)BB*HEADS*NQTOT*NKTOT];
__device__ float g_weighted[(size_t)BB*3*HEADS*NQTOT*VHD];
__device__ float g_rowm[NROWS];
__device__ float g_rowinv[NROWS];
__device__ float g_hid1[(size_t)BB*384*256*256];
__device__ float g_hid2[(size_t)BB*384*256*256];

// fast gelu: 0.5x(1+tanh(0.79788456(x+0.044715x^3))) == x*sigmoid(2z) == x/(1+exp2(-2.3022*v))
__device__ __forceinline__ float gelu_f(float x){
    float u = x*x;
    float v = fmaf(0.044715f*x, u, x);
    float r = exp2f(-2.30220815f*v);
    return __fdividef(x, 1.0f + r);
}

// ---------------- packed f32x2 helpers ----------------
__device__ __forceinline__ unsigned long long pk2(float lo, float hi){
    unsigned long long r; asm("mov.b64 %0, {%1, %2};" : "=l"(r) : "f"(lo), "f"(hi)); return r;
}
__device__ __forceinline__ void upk2(unsigned long long v, float& lo, float& hi){
    asm("mov.b64 {%0, %1}, %2;" : "=f"(lo), "=f"(hi) : "l"(v));
}
#define FFMA2(acc, a, b) asm("fma.rn.f32x2 %0, %1, %2, %3;" : "=l"(acc) : "l"(a), "l"(b), "l"(acc))

// ---------------- tf32 / mma helpers ----------------
__device__ __forceinline__ float to_tf32(float x){
    float r; asm("cvt.rna.tf32.f32 %0, %1;" : "=f"(r) : "f"(x)); return r;
}
__device__ __forceinline__ float4 cvt4(float4 v){
    v.x=to_tf32(v.x); v.y=to_tf32(v.y); v.z=to_tf32(v.z); v.w=to_tf32(v.w); return v;
}
__device__ __forceinline__ float4 exp4(float4 v, float rm, float ri){
    v.x=__expf(v.x-rm)*ri; v.y=__expf(v.y-rm)*ri;
    v.z=__expf(v.z-rm)*ri; v.w=__expf(v.w-rm)*ri; return v;
}
__device__ __forceinline__ void ldsm4(unsigned& r0,unsigned& r1,unsigned& r2,unsigned& r3, const float* p){
    unsigned addr = (unsigned)__cvta_generic_to_shared(p);
    asm volatile("ldmatrix.sync.aligned.m8n8.x4.shared.b16 {%0,%1,%2,%3}, [%4];"
      : "=r"(r0),"=r"(r1),"=r"(r2),"=r"(r3) : "r"(addr));
}
__device__ __forceinline__ void ldsm2(unsigned& r0,unsigned& r1, const float* p){
    unsigned addr = (unsigned)__cvta_generic_to_shared(p);
    asm volatile("ldmatrix.sync.aligned.m8n8.x2.shared.b16 {%0,%1}, [%2];"
      : "=r"(r0),"=r"(r1) : "r"(addr));
}
__device__ __forceinline__ void mma8(float* d, const unsigned* a, unsigned b0, unsigned b1){
    asm volatile("mma.sync.aligned.m16n8k8.row.col.f32.tf32.tf32.f32 "
      "{%0,%1,%2,%3}, {%4,%5,%6,%7}, {%8,%9}, {%0,%1,%2,%3};"
      : "+f"(d[0]),"+f"(d[1]),"+f"(d[2]),"+f"(d[3])
      : "r"(a[0]),"r"(a[1]),"r"(a[2]),"r"(a[3]), "r"(b0),"r"(b1));
}

// ---------------- merged patchify: all 8 images in one launch ----------------
__global__ void k_patchify_all(
    const float* __restrict__ K0, const float* __restrict__ K1, const float* __restrict__ K2,
    const float* __restrict__ V0, const float* __restrict__ V1, const float* __restrict__ V2,
    const float* __restrict__ Q0, const float* __restrict__ Q1,
    float* __restrict__ kseq, float* __restrict__ vseq, float* __restrict__ qseq)
{
    long gidx = (long)blockIdx.x*blockDim.x + threadIdx.x;  // < 17039360 exactly
    const float* src; float* dst;
    int C, Hh, Ww, nOff, Ntot, fd; long base;
    if      (gidx <  2097152){ src=K0; dst=kseq; C=16; Hh=256; Ww=256; nOff=0;    Ntot=NKTOT; fd=KPD; base=0; }
    else if (gidx <  4063232){ src=K1; dst=kseq; C=16; Hh=192; Ww=320; nOff=1024; Ntot=NKTOT; fd=KPD; base=2097152; }
    else if (gidx <  4587520){ src=K2; dst=kseq; C=16; Hh=128; Ww=128; nOff=1984; Ntot=NKTOT; fd=KPD; base=4063232; }
    else if (gidx <  8781824){ src=V0; dst=vseq; C=32; Hh=256; Ww=256; nOff=0;    Ntot=NKTOT; fd=VPD; base=4587520; }
    else if (gidx < 12713984){ src=V1; dst=vseq; C=32; Hh=192; Ww=320; nOff=1024; Ntot=NKTOT; fd=VPD; base=8781824; }
    else if (gidx < 13762560){ src=V2; dst=vseq; C=32; Hh=128; Ww=128; nOff=1984; Ntot=NKTOT; fd=VPD; base=12713984; }
    else if (gidx < 15859712){ src=Q0; dst=qseq; C=16; Hh=256; Ww=256; nOff=0;    Ntot=NQTOT; fd=QPD; base=13762560; }
    else                     { src=Q1; dst=qseq; C=16; Hh=192; Ww=192; nOff=1024; Ntot=NQTOT; fd=QPD; base=15859712; }
    long idx = gidx - base;
    int x = (int)(idx % Ww);
    long t = idx / Ww;
    int y = (int)(t % Hh); t /= Hh;
    int c = (int)(t % C);  int b = (int)(t / C);
    int hp = y>>3, ph = y&7, wp = x>>3, pw = x&7;
    int n = hp*(Ww>>3) + wp;
    int f = ((ph<<3)+pw)*C + c;
    dst[(size_t)(b*Ntot + nOff + n)*fd + f] = src[idx];
}

// ---------------- layernorm rows (in place) ----------------
__global__ void k_layernorm(float* __restrict__ v, const float* __restrict__ g,
                            const float* __restrict__ bta, int dim)
{
    float* p = v + (size_t)blockIdx.x*dim;
    __shared__ float red[256];
    int tid = threadIdx.x;
    float s=0.f, s2=0.f;
    for (int i=tid;i<dim;i+=256){ float x=p[i]; s+=x; s2+=x*x; }
    red[tid]=s; __syncthreads();
    for (int o=128;o>0;o>>=1){ if(tid<o) red[tid]+=red[tid+o]; __syncthreads(); }
    float mean = red[0]/dim; __syncthreads();
    red[tid]=s2; __syncthreads();
    for (int o=128;o>0;o>>=1){ if(tid<o) red[tid]+=red[tid+o]; __syncthreads(); }
    float var = red[0]/dim - mean*mean;
    float rstd = rsqrtf(var + 1e-5f);
    for (int i=tid;i<dim;i+=256){ float x=p[i]; p[i]=(x-mean)*rstd*g[i]+bta[i]; }
}

// =====================================================================
// TF32 MMA GEMM: BM=64, BN=128, BK=32, 256 threads (8 warps 2x4).
// Optional fused softmax-exp on A (DOEXP): a = exp(a - rowm)*rowinv.
// =====================================================================
#define AS_STRIDE 36
#define AS_TILE   (64*AS_STRIDE)
#define BS_STRIDE 132
#define BS_TILE   (32*BS_STRIDE)
#define MMA_SMEM  ((2*AS_TILE + 2*BS_TILE)*4)

template<int ACT, bool HASBIAS, bool DOEXP>
__device__ __forceinline__ void mma_gemm_body(
    const float* __restrict__ A, int lda,
    const float* __restrict__ B, int ldb,
    const float* __restrict__ bias,
    const float* __restrict__ rowm, const float* __restrict__ rowinv,
    float* __restrict__ C, int ldc,
    int K, int bm, int bn)
{
    extern __shared__ float smf[];
    float* As = smf;
    float* Bs = smf + 2*AS_TILE;
    int tid = threadIdx.x;
    int lane = tid & 31, w = tid >> 5;
    int wm = w >> 2, wn = w & 3;          // 2 x 4 warps, warp tile 32x32

    int arow = tid >> 2, acg = (tid & 3) << 3;   // A loader: 64 rows x 32 k
    int bkr  = tid >> 3, bng = (tid & 7) << 4;   // B loader: 32 k x 128 n

    float rm = 0.f, ri = 0.f;
    if (DOEXP){ rm = rowm[bm+arow]; ri = rowinv[bm+arow]; }

    const float* Ap = A + (size_t)(bm + arow)*lda + acg;
    const float* Bp = B + bn + bng;

    int mi = lane >> 3, r8 = lane & 7;
    int abase = (wm*32 + (mi&1)*8 + r8)*AS_STRIDE + (mi>>1)*4;
    int bbase = (lane&3)*BS_STRIDE + wn*32 + (lane>>2);

    float acc[2][4][4];
    #pragma unroll
    for (int i=0;i<2;i++)
        #pragma unroll
        for (int j=0;j<4;j++)
            #pragma unroll
            for (int c=0;c<4;c++) acc[i][j][c]=0.f;

    // prologue: tile 0 -> buf 0
    {
        float4 a0 = *(const float4*)(Ap);
        float4 a1 = *(const float4*)(Ap + 4);
        if (DOEXP){ a0 = exp4(a0, rm, ri); a1 = exp4(a1, rm, ri); }
        *(float4*)&As[arow*AS_STRIDE + acg    ] = cvt4(a0);
        *(float4*)&As[arow*AS_STRIDE + acg + 4] = cvt4(a1);
        const float* bsrc = Bp + (size_t)bkr*ldb;
        #pragma unroll
        for (int j=0;j<4;j++)
            *(float4*)&Bs[bkr*BS_STRIDE + bng + 4*j] = cvt4(*(const float4*)(bsrc + 4*j));
    }
    __syncthreads();

    int buf = 0;
    for (int k0 = 0; k0 < K; k0 += 32){
        bool nxt = (k0 + 32 < K);
        float4 na0, na1, nb0, nb1, nb2, nb3;
        if (nxt){
            na0 = *(const float4*)(Ap + k0 + 32);
            na1 = *(const float4*)(Ap + k0 + 36);
            const float* bsrc = Bp + (size_t)(k0 + 32 + bkr)*ldb;
            nb0 = *(const float4*)(bsrc);
            nb1 = *(const float4*)(bsrc + 4);
            nb2 = *(const float4*)(bsrc + 8);
            nb3 = *(const float4*)(bsrc + 12);
        }
        const float* Ab = As + buf*AS_TILE;
        const float* Bb = Bs + buf*BS_TILE;
        #pragma unroll
        for (int ks=0; ks<4; ks++){
            unsigned a0[4], a1[4];
            ldsm4(a0[0],a0[1],a0[2],a0[3], Ab + abase + ks*8);
            ldsm4(a1[0],a1[1],a1[2],a1[3], Ab + abase + 16*AS_STRIDE + ks*8);
            #pragma unroll
            for (int nf=0; nf<4; nf++){
                const float* bp0 = Bb + bbase + ks*8*BS_STRIDE + nf*8;
                unsigned b0 = __float_as_uint(bp0[0]);
                unsigned b1 = __float_as_uint(bp0[4*BS_STRIDE]);
                mma8(acc[0][nf], a0, b0, b1);
                mma8(acc[1][nf], a1, b0, b1);
            }
        }
        if (nxt){
            int nb = buf ^ 1;
            float* Aw = As + nb*AS_TILE;
            float* Bw = Bs + nb*BS_TILE;
            if (DOEXP){ na0 = exp4(na0, rm, ri); na1 = exp4(na1, rm, ri); }
            *(float4*)&Aw[arow*AS_STRIDE + acg    ] = cvt4(na0);
            *(float4*)&Aw[arow*AS_STRIDE + acg + 4] = cvt4(na1);
            *(float4*)&Bw[bkr*BS_STRIDE + bng     ] = cvt4(nb0);
            *(float4*)&Bw[bkr*BS_STRIDE + bng +  4] = cvt4(nb1);
            *(float4*)&Bw[bkr*BS_STRIDE + bng +  8] = cvt4(nb2);
            *(float4*)&Bw[bkr*BS_STRIDE + bng + 12] = cvt4(nb3);
            __syncthreads();
            buf = nb;
        }
    }

    // epilogue
    int erow = bm + wm*32 + (lane>>2);
    int ecol = bn + wn*32 + (lane&3)*2;
    #pragma unroll
    for (int mf=0; mf<2; mf++){
        int row = erow + mf*16;
        #pragma unroll
        for (int nf=0; nf<4; nf++){
            int col = ecol + nf*8;
            float v0 = acc[mf][nf][0], v1 = acc[mf][nf][1];
            float v2 = acc[mf][nf][2], v3 = acc[mf][nf][3];
            if (HASBIAS){
                float b0v = bias[col], b1v = bias[col+1];
                v0 += b0v; v1 += b1v; v2 += b0v; v3 += b1v;
            }
            if (ACT){ v0=gelu_f(v0); v1=gelu_f(v1); v2=gelu_f(v2); v3=gelu_f(v3); }
            *(float2*)&C[(size_t)row*ldc + col]     = make_float2(v0, v1);
            *(float2*)&C[(size_t)(row+8)*ldc + col] = make_float2(v2, v3);
        }
    }
}

// ---------------- merged K+Q embedding GEMM (z=0: keys, z=1: queries) ----------------
template<int ACT>
__global__ __launch_bounds__(256,2) void k_embed(
    const float* __restrict__ A0, const float* __restrict__ B0, const float* __restrict__ b0, float* __restrict__ C0, int M0,
    const float* __restrict__ A1, const float* __restrict__ B1, const float* __restrict__ b1, float* __restrict__ C1, int M1,
    int K)
{
    int z = blockIdx.z;
    const float* A = z ? A1 : A0;
    const float* B = z ? B1 : B0;
    const float* bi = z ? b1 : b0;
    float* C = z ? C1 : C0;
    int M = z ? M1 : M0;
    int bm = blockIdx.y*64;
    if (bm >= M) return;
    mma_gemm_body<ACT,true,false>(A, K, B, ADIM, bi, nullptr, nullptr, C, ADIM, K, bm, blockIdx.x*128);
}

// ---------------- A*V per (b, seg, head), tf32 mma, softmax-exp fused ----------------
__global__ __launch_bounds__(256,2) void k_av_mma()
{
    int z = blockIdx.z;
    int h = z & 7; int t = z >> 3; int seg = t % 3; int b = t / 3;
    const int segOff[3] = {0, 1024, 1984};
    const int segN[3]   = {1024, 960, 256};
    const float* A = g_scores + (size_t)(b*HEADS + h)*NQTOT*NKTOT + segOff[seg];
    const float* Bv = g_vseq + ((size_t)b*NKTOT + segOff[seg])*VPD + h*VHD;
    const float* rm = g_rowm   + (size_t)(b*HEADS + h)*NQTOT;
    const float* ri = g_rowinv + (size_t)(b*HEADS + h)*NQTOT;
    float* C = g_weighted + (size_t)((b*3 + seg)*HEADS + h)*NQTOT*VHD;
    mma_gemm_body<0,false,true>(A, NKTOT, Bv, VPD, nullptr, rm, ri, C, VHD, segN[seg], blockIdx.y*64, blockIdx.x*128);
}

// ---------------- Q @ K^T (d=32), tf32 mma, 64x64 tile ----------------
__global__ __launch_bounds__(256,2) void k_qk_mma()
{
    __shared__ float Qs[64*AS_STRIDE];
    __shared__ float Ks2[64*AS_STRIDE];
    int z = blockIdx.z; int b = z>>3, h = z&7;
    const float* Aq = g_qemb + (size_t)b*NQTOT*ADIM + h*DH;
    const float* Bk = g_kemb + (size_t)b*NKTOT*ADIM + h*DH;
    float* Sb = g_scores + (size_t)z*NQTOT*NKTOT;
    int tid = threadIdx.x; int lane = tid&31, w = tid>>5;
    int wm = w >> 1, wn = w & 1;   // 4 x 2 warps, warp tile 16x32
    int bm = blockIdx.y*64, bn = blockIdx.x*64;

    int arow = tid>>2, acg = (tid&3)<<3;
    {
        const float* ap = Aq + (size_t)(bm+arow)*ADIM + acg;
        *(float4*)&Qs[arow*AS_STRIDE + acg    ] = cvt4(*(const float4*)ap);
        *(float4*)&Qs[arow*AS_STRIDE + acg + 4] = cvt4(*(const float4*)(ap+4));
        const float* bp = Bk + (size_t)(bn+arow)*ADIM + acg;
        *(float4*)&Ks2[arow*AS_STRIDE + acg    ] = cvt4(*(const float4*)bp);
        *(float4*)&Ks2[arow*AS_STRIDE + acg + 4] = cvt4(*(const float4*)(bp+4));
    }
    __syncthreads();

    int mi = lane>>3, r8 = lane&7;
    int abase = (wm*16 + (mi&1)*8 + r8)*AS_STRIDE + (mi>>1)*4;
    int bl = lane & 15;
    int bbase = (wn*32 + (bl&7))*AS_STRIDE + ((bl>>3)&1)*4;

    float acc[4][4];
    #pragma unroll
    for (int i=0;i<4;i++)
        #pragma unroll
        for (int c=0;c<4;c++) acc[i][c]=0.f;

    #pragma unroll
    for (int ks=0; ks<4; ks++){
        unsigned a[4];
        ldsm4(a[0],a[1],a[2],a[3], Qs + abase + ks*8);
        #pragma unroll
        for (int nf=0; nf<4; nf++){
            unsigned b0, b1;
            ldsm2(b0, b1, Ks2 + bbase + nf*8*AS_STRIDE + ks*8);
            mma8(acc[nf], a, b0, b1);
        }
    }
    const float scale = 0.17677669529663689f; // 1/sqrt(32)
    int erow = bm + wm*16 + (lane>>2);
    int ecol = bn + wn*32 + (lane&3)*2;
    #pragma unroll
    for (int nf=0; nf<4; nf++){
        int col = ecol + nf*8;
        *(float2*)&Sb[(size_t)erow*NKTOT + col]     = make_float2(acc[nf][0]*scale, acc[nf][1]*scale);
        *(float2*)&Sb[(size_t)(erow+8)*NKTOT + col] = make_float2(acc[nf][2]*scale, acc[nf][3]*scale);
    }
}

// ---------------- row stats: max + 1/sum(exp) per score row ----------------
__global__ void k_rowstat()
{
    __shared__ float red[256];
    const float4* p = (const float4*)(g_scores + (size_t)blockIdx.x*NKTOT);
    int tid = threadIdx.x;
    float m = -1e30f;
    for (int i=tid;i<NKTOT/4;i+=256){
        float4 x = p[i];
        m = fmaxf(m, fmaxf(fmaxf(x.x,x.y), fmaxf(x.z,x.w)));
    }
    red[tid]=m; __syncthreads();
    for (int o=128;o>0;o>>=1){ if(tid<o) red[tid]=fmaxf(red[tid],red[tid+o]); __syncthreads(); }
    m = red[0]; __syncthreads();
    float s = 0.f;
    for (int i=tid;i<NKTOT/4;i+=256){
        float4 x = p[i];
        s += __expf(x.x-m) + __expf(x.y-m) + __expf(x.z-m) + __expf(x.w-m);
    }
    red[tid]=s; __syncthreads();
    for (int o=128;o>0;o>>=1){ if(tid<o) red[tid]+=red[tid+o]; __syncthreads(); }
    if (tid==0){ g_rowm[blockIdx.x] = m; g_rowinv[blockIdx.x] = 1.0f/red[0]; }
}

// ---------------- fused assemble + expand (grouped 1x1 96->384 + gelu) ----------------
// Gathers the 12 input channels of group g straight from g_weighted, expands to 48
// hidden channels, writes hid1. 2 px per thread (FFMA2). grid (npix/512, 8, BB).
__global__ __launch_bounds__(256) void k_asm_expand(
    const float* __restrict__ W, const float* __restrict__ wexp,
    const float* __restrict__ bexp, float* __restrict__ H,
    int npix, int qw, int qoff)
{
    __shared__ float ws[48*12];
    __shared__ float bs[48];
    int tid = threadIdx.x;
    int g = blockIdx.y, b = blockIdx.z;
    for (int i=tid;i<576;i+=256) ws[i] = wexp[g*576 + i];
    if (tid < 48) bs[tid] = bexp[g*48 + tid];
    __syncthreads();

    int px0 = blockIdx.x*512 + 2*tid;     // even; px1 = px0+1 same row (qw even)
    int y  = px0 / qw, x = px0 % qw;
    int n0 = (y>>3)*(qw>>3) + (x>>3) + qoff;
    int d0 = (((y&7)<<3) | (x&7)) << 2;
    int x1 = x + 1;
    int n1 = (y>>3)*(qw>>3) + (x1>>3) + qoff;
    int d1 = (((y&7)<<3) | (x1&7)) << 2;

    unsigned long long in[12];
    #pragma unroll
    for (int s=0;s<3;s++){
        size_t row = ((size_t)(b*3+s)*HEADS + g)*NQTOT;
        float4 v0 = *(const float4*)&W[(row + n0)*VHD + d0];
        float4 v1 = *(const float4*)&W[(row + n1)*VHD + d1];
        in[s*4+0] = pk2(v0.x, v1.x);
        in[s*4+1] = pk2(v0.y, v1.y);
        in[s*4+2] = pk2(v0.z, v1.z);
        in[s*4+3] = pk2(v0.w, v1.w);
    }

    float* hout = H + ((size_t)b*384 + g*48)*npix + px0;
    #pragma unroll 4
    for (int o=0;o<48;o++){
        const float* wr = &ws[o*12];
        unsigned long long acc = 0ull;
        #pragma unroll
        for (int i=0;i<12;i++){
            unsigned long long wp = pk2(wr[i], wr[i]);
            FFMA2(acc, in[i], wp);
        }
        float a0, a1;
        upk2(acc, a0, a1);
        float bv = bs[o];
        *(float2*)&hout[(size_t)o*npix] = make_float2(gelu_f(a0+bv), gelu_f(a1+bv));
    }
}

// ---------------- depthwise 7x7 SAME + gelu, FFMA2, 4 px/thread, 32x16 tile ----------
__global__ void k_dw2(const float* __restrict__ H, const float* __restrict__ w,
                      const float* __restrict__ bias, float* __restrict__ O, int Hh, int Ww)
{
    __shared__ float2 PA[22][20];
    __shared__ float2 PB[22][20];
    __shared__ float ws[49];
    int bz = blockIdx.z; int ch = bz % 384; int b = bz / 384;
    const float* in = H + ((size_t)(b*384)+ch)*Hh*Ww;
    int tx = threadIdx.x, ty = threadIdx.y; int tid = ty*8+tx;  // block (8,16)=128
    if (tid < 49) ws[tid] = w[ch*49 + tid];
    int bx = blockIdx.x*32, by = blockIdx.y*16;
    for (int i=tid;i<22*38;i+=128){
        int ly=i/38, lx=i%38;
        int gy=by+ly-3, gx=bx+lx-3;
        float val = (gy>=0 && gy<Hh && gx>=0 && gx<Ww) ? in[(size_t)gy*Ww+gx] : 0.f;
        if ((lx&1)==0){
            PA[ly][lx>>1].x = val;
            if (lx>=2) PB[ly][(lx>>1)-1].y = val;
        } else {
            PA[ly][lx>>1].y = val;
            PB[ly][lx>>1].x = val;
        }
    }
    __syncthreads();

    unsigned long long acc0 = 0ull, acc1 = 0ull;
    int p2 = tx*2;
    #pragma unroll
    for (int ky=0;ky<7;ky++){
        const float2* ra = PA[ty+ky];
        const float2* rb = PB[ty+ky];
        unsigned long long A0 = *(const unsigned long long*)&ra[p2];
        unsigned long long A1 = *(const unsigned long long*)&ra[p2+1];
        unsigned long long A2 = *(const unsigned long long*)&ra[p2+2];
        unsigned long long A3 = *(const unsigned long long*)&ra[p2+3];
        unsigned long long A4 = *(const unsigned long long*)&ra[p2+4];
        unsigned long long B0 = *(const unsigned long long*)&rb[p2];
        unsigned long long B1 = *(const unsigned long long*)&rb[p2+1];
        unsigned long long B2 = *(const unsigned long long*)&rb[p2+2];
        unsigned long long B3 = *(const unsigned long long*)&rb[p2+3];
        float w0=ws[ky*7+0], w1=ws[ky*7+1], w2=ws[ky*7+2], w3=ws[ky*7+3];
        float w4=ws[ky*7+4], w5=ws[ky*7+5], w6=ws[ky*7+6];
        unsigned long long W0=pk2(w0,w0), W1=pk2(w1,w1), W2=pk2(w2,w2), W3=pk2(w3,w3);
        unsigned long long W4=pk2(w4,w4), W5=pk2(w5,w5), W6=pk2(w6,w6);
        FFMA2(acc0, A0, W0); FFMA2(acc1, A1, W0);
        FFMA2(acc0, B0, W1); FFMA2(acc1, B1, W1);
        FFMA2(acc0, A1, W2); FFMA2(acc1, A2, W2);
        FFMA2(acc0, B1, W3); FFMA2(acc1, B2, W3);
        FFMA2(acc0, A2, W4); FFMA2(acc1, A3, W4);
        FFMA2(acc0, B2, W5); FFMA2(acc1, B3, W5);
        FFMA2(acc0, A3, W6); FFMA2(acc1, A4, W6);
    }
    float bsv = bias[ch];
    float o0,o1,o2,o3;
    upk2(acc0, o0, o1); upk2(acc1, o2, o3);
    float4 outv = make_float4(gelu_f(o0+bsv), gelu_f(o1+bsv), gelu_f(o2+bsv), gelu_f(o3+bsv));
    *(float4*)&O[((size_t)(b*384)+ch)*Hh*Ww + (size_t)(by+ty)*Ww + bx + tx*4] = outv;
}

// ---------------- mbconv proj: grouped 1x1 (384->32, groups 8) ----------------
__global__ void k_proj(const float* __restrict__ H, const float* __restrict__ w,
                       const float* __restrict__ bias, float* __restrict__ O, int npix)
{
    __shared__ float ws[32*48];
    int tid = threadIdx.x;
    for (int i=tid;i<1536;i+=256) ws[i]=w[i];
    __syncthreads();
    int pix = blockIdx.x*32 + (tid&31);
    int g = tid>>5;
    int b = blockIdx.y;
    const float* hin = H + ((size_t)b*384 + g*48)*npix + pix;
    float iv[48];
    #pragma unroll
    for (int i=0;i<48;i++) iv[i]=hin[(size_t)i*npix];
    #pragma unroll
    for (int o=0;o<4;o++){
        int oc = g*4 + o;
        const float* wr = &ws[oc*48];
        float s2 = 0.f;
        #pragma unroll
        for (int i=0;i<48;i++) s2 += iv[i]*wr[i];
        O[((size_t)b*32 + oc)*npix + pix] = s2 + bias[oc];
    }
}

// ---------------- host launch ----------------
#define GETSYM(p, sym) do { cudaGetSymbolAddress((void**)&(p), sym); } while(0)

extern "C" void kernel_launch(void* const* d_in, const int* in_sizes, int n_in,
                              void* d_out, int out_size)
{
    bool dictOrder = (in_sizes[1] == 4194304);
    const float* K0 = (const float*)d_in[0];
    const float* V0 = (const float*)d_in[dictOrder ? 1 : 3];
    const float* K1 = (const float*)d_in[dictOrder ? 2 : 1];
    const float* V1 = (const float*)d_in[dictOrder ? 3 : 4];
    const float* K2 = (const float*)d_in[dictOrder ? 4 : 2];
    const float* V2 = (const float*)d_in[5];
    const float* Q0 = (const float*)d_in[6];
    const float* Q1 = (const float*)d_in[7];
    const float* LNG  = (const float*)d_in[8];
    const float* LNB  = (const float*)d_in[9];
    const float* KW1  = (const float*)d_in[10];
    const float* KB1  = (const float*)d_in[11];
    const float* KW2  = (const float*)d_in[12];
    const float* KB2  = (const float*)d_in[13];
    const float* QW1  = (const float*)d_in[14];
    const float* QB1  = (const float*)d_in[15];
    const float* QW2  = (const float*)d_in[16];
    const float* QB2  = (const float*)d_in[17];
    const float* WEXP = (const float*)d_in[18];
    const float* BEXP = (const float*)d_in[19];
    const float* WDW  = (const float*)d_in[20];
    const float* BDW  = (const float*)d_in[21];
    const float* WPRJ = (const float*)d_in[22];
    const float* BPRJ = (const float*)d_in[23];
    float* out = (float*)d_out;

    float *kseq, *vseq, *qseq, *khid, *kemb, *qhid, *qemb, *hid1, *hid2, *wtd;
    GETSYM(kseq, g_kseq); GETSYM(vseq, g_vseq); GETSYM(qseq, g_qseq);
    GETSYM(khid, g_khid); GETSYM(kemb, g_kemb);
    GETSYM(qhid, g_qhid); GETSYM(qemb, g_qemb);
    GETSYM(hid1, g_hid1); GETSYM(hid2, g_hid2);
    GETSYM(wtd, g_weighted);

    cudaFuncSetAttribute((const void*)k_embed<1>, cudaFuncAttributeMaxDynamicSharedMemorySize, MMA_SMEM);
    cudaFuncSetAttribute((const void*)k_embed<0>, cudaFuncAttributeMaxDynamicSharedMemorySize, MMA_SMEM);
    cudaFuncSetAttribute((const void*)k_av_mma,   cudaFuncAttributeMaxDynamicSharedMemorySize, MMA_SMEM);

    // 1) patchify (single merged launch)
    k_patchify_all<<<17039360/256,256>>>(K0,K1,K2,V0,V1,V2,Q0,Q1, kseq, vseq, qseq);

    // 2-3) embeddings (K and Q merged per layer via grid.z)
    k_embed<1><<<dim3(2, 70, 2), 256, MMA_SMEM>>>(
        kseq, KW1, KB1, khid, BB*NKTOT,
        qseq, QW1, QB1, qhid, BB*NQTOT, KPD);
    k_embed<0><<<dim3(2, 70, 2), 256, MMA_SMEM>>>(
        khid, KW2, KB2, kemb, BB*NKTOT,
        qhid, QW2, QB2, qemb, BB*NQTOT, ADIM);

    // 4) QK
    k_qk_mma<<<dim3(NKTOT/64, NQTOT/64, BB*HEADS), 256>>>();

    // 5) row stats
    k_rowstat<<<NROWS,256>>>();

    // 6) layernorm values
    k_layernorm<<<BB*NKTOT,256>>>(vseq, LNG, LNB, VPD);

    // 7) AV with fused softmax-exp
    k_av_mma<<<dim3(2, NQTOT/64, BB*3*HEADS), 256, MMA_SMEM>>>();

    // 8-10) mbconv image 0 (256x256)
    {
        int npix = 256*256;
        k_asm_expand<<<dim3(npix/512, 8, BB),256>>>(wtd, WEXP, BEXP, hid1, npix, 256, 0);
        k_dw2<<<dim3(8, 16, BB*384), dim3(8,16)>>>(hid1, WDW, BDW, hid2, 256, 256);
        k_proj<<<dim3(npix/32, BB),256>>>(hid2, WPRJ, BPRJ, out, npix);
    }
    // 11-13) mbconv image 1 (192x192)
    {
        int npix = 192*192;
        k_asm_expand<<<dim3(npix/512, 8, BB),256>>>(wtd, WEXP, BEXP, hid1, npix, 192, 1024);
        k_dw2<<<dim3(6, 12, BB*384), dim3(8,16)>>>(hid1, WDW, BDW, hid2, 192, 192);
        k_proj<<<dim3(npix/32, BB),256>>>(hid2, WPRJ, BPRJ, out + (size_t)BB*32*256*256, npix);
    }
}